// round 1
// baseline (speedup 1.0000x reference)
#include <cuda_runtime.h>

// ---------------------------------------------------------------------------
// PairInteractionGrid: out[b,t,n*32+m,:] =
//   (silu( [p_n, v_m, p_n*v_m, |p_n-v_m|] @ W1 + b1 )) @ W2 + b2
// with p = price@W_p+b_p, v = liquid@W_v+b_v.
// Restructure: pair@W1 = P1[n] + V1[m] + (p*v)@W1c + |p-v|@W1d
//   where P1 = p@W1[0:128], V1 = v@W1[128:256], W1c = W1[256:384], W1d = W1[384:512]
// All GEMMs via mma.sync.m16n8k8 tf32 (RNA conversion), fp32 accumulate.
// ---------------------------------------------------------------------------

// Scratch (allocation-free rule: __device__ globals)
__device__ float g_p [8192 * 128];
__device__ float g_v [8192 * 128];
__device__ float g_P1[8192 * 128];
__device__ float g_V1[8192 * 128];

__device__ __forceinline__ unsigned f2tf(float x) {
    unsigned r;
    asm("cvt.rna.tf32.f32 %0, %1;" : "=r"(r) : "f"(x));
    return r;
}

__device__ __forceinline__ void mma8(float* c,
                                     unsigned a0, unsigned a1, unsigned a2, unsigned a3,
                                     unsigned b0, unsigned b1) {
    asm volatile(
        "mma.sync.aligned.m16n8k8.row.col.f32.tf32.tf32.f32 "
        "{%0,%1,%2,%3},{%4,%5,%6,%7},{%8,%9},{%0,%1,%2,%3};\n"
        : "+f"(c[0]), "+f"(c[1]), "+f"(c[2]), "+f"(c[3])
        : "r"(a0), "r"(a1), "r"(a2), "r"(a3), "r"(b0), "r"(b1));
}

// ---------------------------------------------------------------------------
// Generic 128x128x128 tile GEMM: C[r][n] = sum_k A[r][k]*W[k][n] + bias[n]
// 128 threads (4 warps), warp w owns rows [32w, 32w+32).
// ---------------------------------------------------------------------------
__device__ void gemm_tile(const float* __restrict__ Arow0,
                          const float* __restrict__ Wkn,
                          const float* __restrict__ bias,
                          float* __restrict__ Crow0,
                          unsigned* A_s, unsigned* W_s) {
    const int tid = threadIdx.x;
    const int w = tid >> 5, lane = tid & 31;
    const int gid = lane >> 2, t4 = lane & 3;

    float acc[2][16][4];
#pragma unroll
    for (int mi = 0; mi < 2; mi++)
#pragma unroll
        for (int j = 0; j < 16; j++)
#pragma unroll
            for (int e = 0; e < 4; e++) acc[mi][j][e] = 0.f;

    for (int s = 0; s < 4; s++) {
        if (s) __syncthreads();
        for (int idx = tid; idx < 4096; idx += 128) {
            int r = idx >> 5, kk = idx & 31;
            A_s[r * 33 + kk] = f2tf(Arow0[r * 128 + s * 32 + kk]);
        }
        for (int idx = tid; idx < 4096; idx += 128) {
            int kk = idx >> 7, n = idx & 127;
            W_s[kk * 129 + n] = f2tf(Wkn[(s * 32 + kk) * 128 + n]);
        }
        __syncthreads();
#pragma unroll
        for (int ks = 0; ks < 4; ks++) {
            const int kb = ks * 8;
            unsigned a[2][4];
#pragma unroll
            for (int mi = 0; mi < 2; mi++) {
                int rb = w * 32 + mi * 16;
                a[mi][0] = A_s[(rb + gid) * 33 + kb + t4];
                a[mi][1] = A_s[(rb + gid + 8) * 33 + kb + t4];
                a[mi][2] = A_s[(rb + gid) * 33 + kb + t4 + 4];
                a[mi][3] = A_s[(rb + gid + 8) * 33 + kb + t4 + 4];
            }
#pragma unroll
            for (int j = 0; j < 16; j++) {
                unsigned b0 = W_s[(kb + t4) * 129 + j * 8 + gid];
                unsigned b1 = W_s[(kb + t4 + 4) * 129 + j * 8 + gid];
                mma8(acc[0][j], a[0][0], a[0][1], a[0][2], a[0][3], b0, b1);
                mma8(acc[1][j], a[1][0], a[1][1], a[1][2], a[1][3], b0, b1);
            }
        }
    }
#pragma unroll
    for (int mi = 0; mi < 2; mi++) {
        int r0 = w * 32 + mi * 16 + gid;
#pragma unroll
        for (int j = 0; j < 16; j++) {
            int col = j * 8 + 2 * t4;
            float bv0 = bias ? bias[col] : 0.f;
            float bv1 = bias ? bias[col + 1] : 0.f;
            float2 v0 = make_float2(acc[mi][j][0] + bv0, acc[mi][j][1] + bv1);
            float2 v1 = make_float2(acc[mi][j][2] + bv0, acc[mi][j][3] + bv1);
            *(float2*)&Crow0[r0 * 128 + col] = v0;
            *(float2*)&Crow0[(r0 + 8) * 128 + col] = v1;
        }
    }
}

__global__ __launch_bounds__(128) void gemm_pv_kernel(
    const float* __restrict__ price, const float* __restrict__ liquid,
    const float* __restrict__ W_p, const float* __restrict__ b_p,
    const float* __restrict__ W_v, const float* __restrict__ b_v) {
    __shared__ unsigned A_s[128 * 33];
    __shared__ unsigned W_s[32 * 129];
    int cb = blockIdx.x;
    if (cb < 64) {
        gemm_tile(price + cb * 128 * 128, W_p, b_p, g_p + cb * 128 * 128, A_s, W_s);
    } else {
        int c = cb - 64;
        gemm_tile(liquid + c * 128 * 128, W_v, b_v, g_v + c * 128 * 128, A_s, W_s);
    }
}

__global__ __launch_bounds__(128) void gemm_p1v1_kernel(const float* __restrict__ W1) {
    __shared__ unsigned A_s[128 * 33];
    __shared__ unsigned W_s[32 * 129];
    int cb = blockIdx.x;
    if (cb < 64) {
        gemm_tile(g_p + cb * 128 * 128, W1, nullptr, g_P1 + cb * 128 * 128, A_s, W_s);
    } else {
        int c = cb - 64;
        gemm_tile(g_v + c * 128 * 128, W1 + 128 * 128, nullptr, g_V1 + c * 128 * 128, A_s, W_s);
    }
}

// ---------------------------------------------------------------------------
// Main kernel: one CTA per (bt, 128-pair block). 128 threads, 4 warps.
// smem layout (floats):
//   union [0, 16896):  phase1: v_s(4128) V1_s(4128) A_s(4224 u32) W_s(4128 u32)
//                      phase2: h_s 128x132
//   p_s 516, P1_s 516, b1_s 128, b2_s 128, W2_s 4128 (u32)
// total 22312 floats = 89248 bytes -> 2 CTAs/SM
// ---------------------------------------------------------------------------
__global__ __launch_bounds__(128) void pair_main_kernel(
    const float* __restrict__ W1, const float* __restrict__ b1v,
    const float* __restrict__ W2, const float* __restrict__ b2v,
    float* __restrict__ out) {
    extern __shared__ float sm[];
    float*    v_s  = sm;
    float*    V1_s = sm + 4128;
    unsigned* A_s  = (unsigned*)(sm + 8256);
    unsigned* W_s  = (unsigned*)(sm + 12480);
    float*    h_s  = sm;                       // aliases phase-1 buffers
    float*    p_s  = sm + 16896;
    float*    P1_s = p_s + 516;
    float*    b1_s = P1_s + 516;
    float*    b2_s = b1_s + 128;
    unsigned* W2_s = (unsigned*)(b2_s + 128);

    const int bt = blockIdx.x >> 3, pb = blockIdx.x & 7;
    const int tid = threadIdx.x;
    const int w = tid >> 5, lane = tid & 31;
    const int gid = lane >> 2, t4 = lane & 3;

    {
        const float* vg  = g_v  + bt * 32 * 128;
        const float* V1g = g_V1 + bt * 32 * 128;
        for (int idx = tid; idx < 4096; idx += 128) {
            int m = idx >> 7, k = idx & 127;
            v_s [m * 129 + k] = vg [m * 128 + k];
            V1_s[m * 129 + k] = V1g[m * 128 + k];
        }
        const float* pg  = g_p  + (bt * 32 + pb * 4) * 128;
        const float* P1g = g_P1 + (bt * 32 + pb * 4) * 128;
        for (int idx = tid; idx < 512; idx += 128) {
            int n = idx >> 7, k = idx & 127;
            p_s [n * 129 + k] = pg [n * 128 + k];
            P1_s[n * 129 + k] = P1g[n * 128 + k];
        }
        b1_s[tid] = b1v[tid];
        b2_s[tid] = b2v[tid];
    }
    __syncthreads();

    float acc[2][16][4];
#pragma unroll
    for (int mi = 0; mi < 2; mi++)
#pragma unroll
        for (int j = 0; j < 16; j++)
#pragma unroll
            for (int e = 0; e < 4; e++) acc[mi][j][e] = 0.f;

    // ------------------ GEMM1: K=256 ([prod | absdiff] @ [W1c; W1d]) -------
    for (int s = 0; s < 8; s++) {
        if (s) __syncthreads();
        {
            // build A slab: row r = tid -> (n = r>>5 local, m = r&31)
            int n = tid >> 5, m = tid & 31;
            const float* pr = &p_s[n * 129];
            const float* vr = &v_s[m * 129];
            int kb = (s & 3) * 32;
            if (s < 4) {
#pragma unroll
                for (int kk = 0; kk < 32; kk++)
                    A_s[tid * 33 + kk] = f2tf(pr[kb + kk] * vr[kb + kk]);
            } else {
#pragma unroll
                for (int kk = 0; kk < 32; kk++)
                    A_s[tid * 33 + kk] = f2tf(fabsf(pr[kb + kk] - vr[kb + kk]));
            }
        }
        for (int idx = tid; idx < 4096; idx += 128) {
            int kk = idx >> 7, n = idx & 127;
            W_s[kk * 129 + n] = f2tf(W1[(256 + s * 32 + kk) * 128 + n]);
        }
        __syncthreads();
#pragma unroll
        for (int ks = 0; ks < 4; ks++) {
            const int kb = ks * 8;
            unsigned a[2][4];
#pragma unroll
            for (int mi = 0; mi < 2; mi++) {
                int rb = w * 32 + mi * 16;
                a[mi][0] = A_s[(rb + gid) * 33 + kb + t4];
                a[mi][1] = A_s[(rb + gid + 8) * 33 + kb + t4];
                a[mi][2] = A_s[(rb + gid) * 33 + kb + t4 + 4];
                a[mi][3] = A_s[(rb + gid + 8) * 33 + kb + t4 + 4];
            }
#pragma unroll
            for (int j = 0; j < 16; j++) {
                unsigned b0 = W_s[(kb + t4) * 129 + j * 8 + gid];
                unsigned b1 = W_s[(kb + t4 + 4) * 129 + j * 8 + gid];
                mma8(acc[0][j], a[0][0], a[0][1], a[0][2], a[0][3], b0, b1);
                mma8(acc[1][j], a[1][0], a[1][1], a[1][2], a[1][3], b0, b1);
            }
        }
    }

    // ------------- epilogue 1: + P1[n] + V1[m] + b1, SiLU ------------------
#pragma unroll
    for (int mi = 0; mi < 2; mi++) {
        int r0 = w * 32 + mi * 16 + gid, r1 = r0 + 8;
        int n0 = r0 >> 5, m0 = r0 & 31, n1 = r1 >> 5, m1 = r1 & 31;
#pragma unroll
        for (int j = 0; j < 16; j++) {
            int col = j * 8 + 2 * t4;
#pragma unroll
            for (int e = 0; e < 4; e++) {
                int nn = (e < 2) ? n0 : n1;
                int mm = (e < 2) ? m0 : m1;
                int cc = col + (e & 1);
                float x = acc[mi][j][e] + P1_s[nn * 129 + cc] + V1_s[mm * 129 + cc] + b1_s[cc];
                acc[mi][j][e] = x / (1.f + __expf(-x));  // silu
            }
        }
    }
    __syncthreads();  // all reads of v/V1/A/W done -> safe to alias with h_s

    // stage h to smem (warp-local rows)
#pragma unroll
    for (int mi = 0; mi < 2; mi++) {
        int r0 = w * 32 + mi * 16 + gid, r1 = r0 + 8;
#pragma unroll
        for (int j = 0; j < 16; j++) {
            int col = j * 8 + 2 * t4;
            h_s[r0 * 132 + col]     = acc[mi][j][0];
            h_s[r0 * 132 + col + 1] = acc[mi][j][1];
            h_s[r1 * 132 + col]     = acc[mi][j][2];
            h_s[r1 * 132 + col + 1] = acc[mi][j][3];
        }
    }
#pragma unroll
    for (int mi = 0; mi < 2; mi++)
#pragma unroll
        for (int j = 0; j < 16; j++)
#pragma unroll
            for (int e = 0; e < 4; e++) acc[mi][j][e] = 0.f;

    // ------------------ GEMM2: h(128x128) @ W2(128x128) --------------------
    for (int s = 0; s < 4; s++) {
        __syncthreads();
        for (int idx = tid; idx < 4096; idx += 128) {
            int kk = idx >> 7, n = idx & 127;
            W2_s[kk * 129 + n] = f2tf(W2[(s * 32 + kk) * 128 + n]);
        }
        __syncthreads();
#pragma unroll
        for (int ks = 0; ks < 4; ks++) {
            const int kg = s * 32 + ks * 8;  // global k into h
            const int kb = ks * 8;           // local k into W2 slab
            unsigned a[2][4];
#pragma unroll
            for (int mi = 0; mi < 2; mi++) {
                int rb = w * 32 + mi * 16;
                a[mi][0] = f2tf(h_s[(rb + gid) * 132 + kg + t4]);
                a[mi][1] = f2tf(h_s[(rb + gid + 8) * 132 + kg + t4]);
                a[mi][2] = f2tf(h_s[(rb + gid) * 132 + kg + t4 + 4]);
                a[mi][3] = f2tf(h_s[(rb + gid + 8) * 132 + kg + t4 + 4]);
            }
#pragma unroll
            for (int j = 0; j < 16; j++) {
                unsigned b0 = W2_s[(kb + t4) * 129 + j * 8 + gid];
                unsigned b1 = W2_s[(kb + t4 + 4) * 129 + j * 8 + gid];
                mma8(acc[0][j], a[0][0], a[0][1], a[0][2], a[0][3], b0, b1);
                mma8(acc[1][j], a[1][0], a[1][1], a[1][2], a[1][3], b0, b1);
            }
        }
    }

    // ------------- epilogue 2: + b2, coalesced store via smem --------------
    __syncwarp();  // warp-local h rows: all lanes done reading before overwrite
#pragma unroll
    for (int mi = 0; mi < 2; mi++) {
        int r0 = w * 32 + mi * 16 + gid, r1 = r0 + 8;
#pragma unroll
        for (int j = 0; j < 16; j++) {
            int col = j * 8 + 2 * t4;
            h_s[r0 * 132 + col]     = acc[mi][j][0] + b2_s[col];
            h_s[r0 * 132 + col + 1] = acc[mi][j][1] + b2_s[col + 1];
            h_s[r1 * 132 + col]     = acc[mi][j][2] + b2_s[col];
            h_s[r1 * 132 + col + 1] = acc[mi][j][3] + b2_s[col + 1];
        }
    }
    __syncwarp();

    const long base = ((long)bt * 1024 + pb * 128 + w * 32) * 128;
#pragma unroll 4
    for (int rr = 0; rr < 32; rr++) {
        float4 val = *(float4*)&h_s[(w * 32 + rr) * 132 + lane * 4];
        *(float4*)&out[base + rr * 128 + lane * 4] = val;
    }
}

// ---------------------------------------------------------------------------
extern "C" void kernel_launch(void* const* d_in, const int* in_sizes, int n_in,
                              void* d_out, int out_size) {
    const float* price  = (const float*)d_in[0];
    const float* liquid = (const float*)d_in[1];
    const float* W_p    = (const float*)d_in[2];
    const float* b_p    = (const float*)d_in[3];
    const float* W_v    = (const float*)d_in[4];
    const float* b_v    = (const float*)d_in[5];
    const float* W1     = (const float*)d_in[6];
    const float* b1     = (const float*)d_in[7];
    const float* W2     = (const float*)d_in[8];
    const float* b2     = (const float*)d_in[9];
    float* out = (float*)d_out;

    cudaFuncSetAttribute(pair_main_kernel,
                         cudaFuncAttributeMaxDynamicSharedMemorySize, 90112);

    gemm_pv_kernel<<<128, 128>>>(price, liquid, W_p, b_p, W_v, b_v);
    gemm_p1v1_kernel<<<128, 128>>>(W1);
    pair_main_kernel<<<2048, 128, 89248>>>(W1, b1, W2, b2, out);
}

// round 2
// speedup vs baseline: 1.0163x; 1.0163x over previous
#include <cuda_runtime.h>

// ---------------------------------------------------------------------------
// PairInteractionGrid: out[b,t,n*32+m,:] =
//   (silu( [p_n, v_m, p_n*v_m, |p_n-v_m|] @ W1 + b1 )) @ W2 + b2
// with p = price@W_p+b_p, v = liquid@W_v+b_v.
// Restructure: pair@W1 = P1[n] + V1[m] + (p*v)@W1c + |p-v|@W1d
//   where P1 = p@W1[0:128], V1 = v@W1[128:256], W1c = W1[256:384], W1d = W1[384:512]
// All GEMMs via mma.sync.m16n8k8 tf32 (RNA conversion), fp32 accumulate.
// ---------------------------------------------------------------------------

// Scratch (allocation-free rule: __device__ globals)
__device__ float g_p [8192 * 128];
__device__ float g_v [8192 * 128];
__device__ float g_P1[8192 * 128];
__device__ float g_V1[8192 * 128];

__device__ __forceinline__ unsigned f2tf(float x) {
    unsigned r;
    asm("cvt.rna.tf32.f32 %0, %1;" : "=r"(r) : "f"(x));
    return r;
}

__device__ __forceinline__ void mma8(float* c,
                                     unsigned a0, unsigned a1, unsigned a2, unsigned a3,
                                     unsigned b0, unsigned b1) {
    asm volatile(
        "mma.sync.aligned.m16n8k8.row.col.f32.tf32.tf32.f32 "
        "{%0,%1,%2,%3},{%4,%5,%6,%7},{%8,%9},{%0,%1,%2,%3};\n"
        : "+f"(c[0]), "+f"(c[1]), "+f"(c[2]), "+f"(c[3])
        : "r"(a0), "r"(a1), "r"(a2), "r"(a3), "r"(b0), "r"(b1));
}

// ---------------------------------------------------------------------------
// Generic 128x128x128 tile GEMM: C[r][n] = sum_k A[r][k]*W[k][n] + bias[n]
// 128 threads (4 warps), warp w owns rows [32w, 32w+32).
// ---------------------------------------------------------------------------
__device__ void gemm_tile(const float* __restrict__ Arow0,
                          const float* __restrict__ Wkn,
                          const float* __restrict__ bias,
                          float* __restrict__ Crow0,
                          unsigned* A_s, unsigned* W_s) {
    const int tid = threadIdx.x;
    const int w = tid >> 5, lane = tid & 31;
    const int gid = lane >> 2, t4 = lane & 3;

    float acc[2][16][4];
#pragma unroll
    for (int mi = 0; mi < 2; mi++)
#pragma unroll
        for (int j = 0; j < 16; j++)
#pragma unroll
            for (int e = 0; e < 4; e++) acc[mi][j][e] = 0.f;

    for (int s = 0; s < 4; s++) {
        if (s) __syncthreads();
        for (int idx = tid; idx < 4096; idx += 128) {
            int r = idx >> 5, kk = idx & 31;
            A_s[r * 33 + kk] = f2tf(Arow0[r * 128 + s * 32 + kk]);
        }
        for (int idx = tid; idx < 4096; idx += 128) {
            int kk = idx >> 7, n = idx & 127;
            W_s[kk * 129 + n] = f2tf(Wkn[(s * 32 + kk) * 128 + n]);
        }
        __syncthreads();
#pragma unroll
        for (int ks = 0; ks < 4; ks++) {
            const int kb = ks * 8;
            unsigned a[2][4];
#pragma unroll
            for (int mi = 0; mi < 2; mi++) {
                int rb = w * 32 + mi * 16;
                a[mi][0] = A_s[(rb + gid) * 33 + kb + t4];
                a[mi][1] = A_s[(rb + gid + 8) * 33 + kb + t4];
                a[mi][2] = A_s[(rb + gid) * 33 + kb + t4 + 4];
                a[mi][3] = A_s[(rb + gid + 8) * 33 + kb + t4 + 4];
            }
#pragma unroll
            for (int j = 0; j < 16; j++) {
                unsigned b0 = W_s[(kb + t4) * 129 + j * 8 + gid];
                unsigned b1 = W_s[(kb + t4 + 4) * 129 + j * 8 + gid];
                mma8(acc[0][j], a[0][0], a[0][1], a[0][2], a[0][3], b0, b1);
                mma8(acc[1][j], a[1][0], a[1][1], a[1][2], a[1][3], b0, b1);
            }
        }
    }
#pragma unroll
    for (int mi = 0; mi < 2; mi++) {
        int r0 = w * 32 + mi * 16 + gid;
#pragma unroll
        for (int j = 0; j < 16; j++) {
            int col = j * 8 + 2 * t4;
            float bv0 = bias ? bias[col] : 0.f;
            float bv1 = bias ? bias[col + 1] : 0.f;
            float2 v0 = make_float2(acc[mi][j][0] + bv0, acc[mi][j][1] + bv1);
            float2 v1 = make_float2(acc[mi][j][2] + bv0, acc[mi][j][3] + bv1);
            *(float2*)&Crow0[r0 * 128 + col] = v0;
            *(float2*)&Crow0[(r0 + 8) * 128 + col] = v1;
        }
    }
}

__global__ __launch_bounds__(128) void gemm_pv_kernel(
    const float* __restrict__ price, const float* __restrict__ liquid,
    const float* __restrict__ W_p, const float* __restrict__ b_p,
    const float* __restrict__ W_v, const float* __restrict__ b_v) {
    __shared__ unsigned A_s[128 * 33];
    __shared__ unsigned W_s[32 * 129];
    int cb = blockIdx.x;
    if (cb < 64) {
        gemm_tile(price + cb * 128 * 128, W_p, b_p, g_p + cb * 128 * 128, A_s, W_s);
    } else {
        int c = cb - 64;
        gemm_tile(liquid + c * 128 * 128, W_v, b_v, g_v + c * 128 * 128, A_s, W_s);
    }
}

__global__ __launch_bounds__(128) void gemm_p1v1_kernel(const float* __restrict__ W1) {
    __shared__ unsigned A_s[128 * 33];
    __shared__ unsigned W_s[32 * 129];
    int cb = blockIdx.x;
    if (cb < 64) {
        gemm_tile(g_p + cb * 128 * 128, W1, nullptr, g_P1 + cb * 128 * 128, A_s, W_s);
    } else {
        int c = cb - 64;
        gemm_tile(g_v + c * 128 * 128, W1 + 128 * 128, nullptr, g_V1 + c * 128 * 128, A_s, W_s);
    }
}

// ---------------------------------------------------------------------------
// Main kernel: one CTA per (bt, 128-pair block). 128 threads, 4 warps.
// smem layout (floats):
//   union [0, 16896):  phase1: v_s(4128) V1_s(4128) A_s(4224 u32) W_s(4128 u32)
//                      phase2: h_s 128x132
//   p_s 516, P1_s 516, b1_s 128, b2_s 128, W2_s 4128 (u32)
// total 22312 floats = 89248 bytes -> 2 CTAs/SM
// ---------------------------------------------------------------------------
__global__ __launch_bounds__(128) void pair_main_kernel(
    const float* __restrict__ W1, const float* __restrict__ b1v,
    const float* __restrict__ W2, const float* __restrict__ b2v,
    float* __restrict__ out) {
    extern __shared__ float sm[];
    float*    v_s  = sm;
    float*    V1_s = sm + 4128;
    unsigned* A_s  = (unsigned*)(sm + 8256);
    unsigned* W_s  = (unsigned*)(sm + 12480);
    float*    h_s  = sm;                       // aliases phase-1 buffers
    float*    p_s  = sm + 16896;
    float*    P1_s = p_s + 516;
    float*    b1_s = P1_s + 516;
    float*    b2_s = b1_s + 128;
    unsigned* W2_s = (unsigned*)(b2_s + 128);

    const int bt = blockIdx.x >> 3, pb = blockIdx.x & 7;
    const int tid = threadIdx.x;
    const int w = tid >> 5, lane = tid & 31;
    const int gid = lane >> 2, t4 = lane & 3;

    {
        const float* vg  = g_v  + bt * 32 * 128;
        const float* V1g = g_V1 + bt * 32 * 128;
        for (int idx = tid; idx < 4096; idx += 128) {
            int m = idx >> 7, k = idx & 127;
            v_s [m * 129 + k] = vg [m * 128 + k];
            V1_s[m * 129 + k] = V1g[m * 128 + k];
        }
        const float* pg  = g_p  + (bt * 32 + pb * 4) * 128;
        const float* P1g = g_P1 + (bt * 32 + pb * 4) * 128;
        for (int idx = tid; idx < 512; idx += 128) {
            int n = idx >> 7, k = idx & 127;
            p_s [n * 129 + k] = pg [n * 128 + k];
            P1_s[n * 129 + k] = P1g[n * 128 + k];
        }
        b1_s[tid] = b1v[tid];
        b2_s[tid] = b2v[tid];
    }
    __syncthreads();

    float acc[2][16][4];
#pragma unroll
    for (int mi = 0; mi < 2; mi++)
#pragma unroll
        for (int j = 0; j < 16; j++)
#pragma unroll
            for (int e = 0; e < 4; e++) acc[mi][j][e] = 0.f;

    // ------------------ GEMM1: K=256 ([prod | absdiff] @ [W1c; W1d]) -------
    for (int s = 0; s < 8; s++) {
        if (s) __syncthreads();
        {
            // build A slab: row r = tid -> (n = r>>5 local, m = r&31)
            int n = tid >> 5, m = tid & 31;
            const float* pr = &p_s[n * 129];
            const float* vr = &v_s[m * 129];
            int kb = (s & 3) * 32;
            if (s < 4) {
#pragma unroll
                for (int kk = 0; kk < 32; kk++)
                    A_s[tid * 33 + kk] = f2tf(pr[kb + kk] * vr[kb + kk]);
            } else {
#pragma unroll
                for (int kk = 0; kk < 32; kk++)
                    A_s[tid * 33 + kk] = f2tf(fabsf(pr[kb + kk] - vr[kb + kk]));
            }
        }
        for (int idx = tid; idx < 4096; idx += 128) {
            int kk = idx >> 7, n = idx & 127;
            W_s[kk * 129 + n] = f2tf(W1[(256 + s * 32 + kk) * 128 + n]);
        }
        __syncthreads();
#pragma unroll
        for (int ks = 0; ks < 4; ks++) {
            const int kb = ks * 8;
            unsigned a[2][4];
#pragma unroll
            for (int mi = 0; mi < 2; mi++) {
                int rb = w * 32 + mi * 16;
                a[mi][0] = A_s[(rb + gid) * 33 + kb + t4];
                a[mi][1] = A_s[(rb + gid + 8) * 33 + kb + t4];
                a[mi][2] = A_s[(rb + gid) * 33 + kb + t4 + 4];
                a[mi][3] = A_s[(rb + gid + 8) * 33 + kb + t4 + 4];
            }
#pragma unroll
            for (int j = 0; j < 16; j++) {
                unsigned b0 = W_s[(kb + t4) * 129 + j * 8 + gid];
                unsigned b1 = W_s[(kb + t4 + 4) * 129 + j * 8 + gid];
                mma8(acc[0][j], a[0][0], a[0][1], a[0][2], a[0][3], b0, b1);
                mma8(acc[1][j], a[1][0], a[1][1], a[1][2], a[1][3], b0, b1);
            }
        }
    }

    // ------------- epilogue 1: + P1[n] + V1[m] + b1, SiLU ------------------
#pragma unroll
    for (int mi = 0; mi < 2; mi++) {
        int r0 = w * 32 + mi * 16 + gid, r1 = r0 + 8;
        int n0 = r0 >> 5, m0 = r0 & 31, n1 = r1 >> 5, m1 = r1 & 31;
#pragma unroll
        for (int j = 0; j < 16; j++) {
            int col = j * 8 + 2 * t4;
#pragma unroll
            for (int e = 0; e < 4; e++) {
                int nn = (e < 2) ? n0 : n1;
                int mm = (e < 2) ? m0 : m1;
                int cc = col + (e & 1);
                float x = acc[mi][j][e] + P1_s[nn * 129 + cc] + V1_s[mm * 129 + cc] + b1_s[cc];
                acc[mi][j][e] = x / (1.f + __expf(-x));  // silu
            }
        }
    }
    __syncthreads();  // all reads of v/V1/A/W done -> safe to alias with h_s

    // stage h to smem (warp-local rows)
#pragma unroll
    for (int mi = 0; mi < 2; mi++) {
        int r0 = w * 32 + mi * 16 + gid, r1 = r0 + 8;
#pragma unroll
        for (int j = 0; j < 16; j++) {
            int col = j * 8 + 2 * t4;
            h_s[r0 * 132 + col]     = acc[mi][j][0];
            h_s[r0 * 132 + col + 1] = acc[mi][j][1];
            h_s[r1 * 132 + col]     = acc[mi][j][2];
            h_s[r1 * 132 + col + 1] = acc[mi][j][3];
        }
    }
#pragma unroll
    for (int mi = 0; mi < 2; mi++)
#pragma unroll
        for (int j = 0; j < 16; j++)
#pragma unroll
            for (int e = 0; e < 4; e++) acc[mi][j][e] = 0.f;

    // ------------------ GEMM2: h(128x128) @ W2(128x128) --------------------
    for (int s = 0; s < 4; s++) {
        __syncthreads();
        for (int idx = tid; idx < 4096; idx += 128) {
            int kk = idx >> 7, n = idx & 127;
            W2_s[kk * 129 + n] = f2tf(W2[(s * 32 + kk) * 128 + n]);
        }
        __syncthreads();
#pragma unroll
        for (int ks = 0; ks < 4; ks++) {
            const int kg = s * 32 + ks * 8;  // global k into h
            const int kb = ks * 8;           // local k into W2 slab
            unsigned a[2][4];
#pragma unroll
            for (int mi = 0; mi < 2; mi++) {
                int rb = w * 32 + mi * 16;
                a[mi][0] = f2tf(h_s[(rb + gid) * 132 + kg + t4]);
                a[mi][1] = f2tf(h_s[(rb + gid + 8) * 132 + kg + t4]);
                a[mi][2] = f2tf(h_s[(rb + gid) * 132 + kg + t4 + 4]);
                a[mi][3] = f2tf(h_s[(rb + gid + 8) * 132 + kg + t4 + 4]);
            }
#pragma unroll
            for (int j = 0; j < 16; j++) {
                unsigned b0 = W2_s[(kb + t4) * 129 + j * 8 + gid];
                unsigned b1 = W2_s[(kb + t4 + 4) * 129 + j * 8 + gid];
                mma8(acc[0][j], a[0][0], a[0][1], a[0][2], a[0][3], b0, b1);
                mma8(acc[1][j], a[1][0], a[1][1], a[1][2], a[1][3], b0, b1);
            }
        }
    }

    // ------------- epilogue 2: + b2, coalesced store via smem --------------
    __syncwarp();  // warp-local h rows: all lanes done reading before overwrite
#pragma unroll
    for (int mi = 0; mi < 2; mi++) {
        int r0 = w * 32 + mi * 16 + gid, r1 = r0 + 8;
#pragma unroll
        for (int j = 0; j < 16; j++) {
            int col = j * 8 + 2 * t4;
            h_s[r0 * 132 + col]     = acc[mi][j][0] + b2_s[col];
            h_s[r0 * 132 + col + 1] = acc[mi][j][1] + b2_s[col + 1];
            h_s[r1 * 132 + col]     = acc[mi][j][2] + b2_s[col];
            h_s[r1 * 132 + col + 1] = acc[mi][j][3] + b2_s[col + 1];
        }
    }
    __syncwarp();

    const long base = ((long)bt * 1024 + pb * 128 + w * 32) * 128;
#pragma unroll 4
    for (int rr = 0; rr < 32; rr++) {
        float4 val = *(float4*)&h_s[(w * 32 + rr) * 132 + lane * 4];
        *(float4*)&out[base + rr * 128 + lane * 4] = val;
    }
}

// ---------------------------------------------------------------------------
extern "C" void kernel_launch(void* const* d_in, const int* in_sizes, int n_in,
                              void* d_out, int out_size) {
    const float* price  = (const float*)d_in[0];
    const float* liquid = (const float*)d_in[1];
    const float* W_p    = (const float*)d_in[2];
    const float* b_p    = (const float*)d_in[3];
    const float* W_v    = (const float*)d_in[4];
    const float* b_v    = (const float*)d_in[5];
    const float* W1     = (const float*)d_in[6];
    const float* b1     = (const float*)d_in[7];
    const float* W2     = (const float*)d_in[8];
    const float* b2     = (const float*)d_in[9];
    float* out = (float*)d_out;

    cudaFuncSetAttribute(pair_main_kernel,
                         cudaFuncAttributeMaxDynamicSharedMemorySize, 90112);

    gemm_pv_kernel<<<128, 128>>>(price, liquid, W_p, b_p, W_v, b_v);
    gemm_p1v1_kernel<<<128, 128>>>(W1);
    pair_main_kernel<<<2048, 128, 89248>>>(W1, b1, W2, b2, out);
}

// round 3
// speedup vs baseline: 1.9627x; 1.9312x over previous
#include <cuda_runtime.h>
#include <cstdint>

#define DI __device__ __forceinline__

// ---------------- scratch globals (allocation-free rule) -------------------
__device__ float g_p [8192 * 128];
__device__ float g_v [8192 * 128];
__device__ float g_P1[8192 * 128];
__device__ float g_V1[8192 * 128];
__device__ float g_Wfp[128 * 128];     // W_p @ W1a
__device__ float g_Wfv[128 * 128];     // W_v @ W1b
__device__ float g_biasF[2 * 128];     // b_p@W1a , b_v@W1b

// tf32 fragment-packed weights: slab = [kstep(4) x lane(32)] x 36 (stride pad)
__device__ __align__(16) unsigned g_W1f [8 * 4608];   // W1c|W1d (rows 256..511)
__device__ __align__(16) unsigned g_W2f [4 * 4608];
__device__ __align__(16) unsigned g_Wpf [4 * 4608];
__device__ __align__(16) unsigned g_Wfpf[4 * 4608];
__device__ __align__(16) unsigned g_Wvf [4 * 4608];
__device__ __align__(16) unsigned g_Wfvf[4 * 4608];

DI unsigned f2tf(float x) {
    unsigned r;
    asm("cvt.rna.tf32.f32 %0, %1;" : "=r"(r) : "f"(x));
    return r;
}
DI void mma8(float* c, unsigned a0, unsigned a1, unsigned a2, unsigned a3,
             unsigned b0, unsigned b1) {
    asm volatile(
        "mma.sync.aligned.m16n8k8.row.col.f32.tf32.tf32.f32 "
        "{%0,%1,%2,%3},{%4,%5,%6,%7},{%8,%9},{%0,%1,%2,%3};\n"
        : "+f"(c[0]), "+f"(c[1]), "+f"(c[2]), "+f"(c[3])
        : "r"(a0), "r"(a1), "r"(a2), "r"(a3), "r"(b0), "r"(b1));
}
DI void cp16(uint32_t smem, const void* gmem) {
    asm volatile("cp.async.cg.shared.global [%0], [%1], 16;\n" :: "r"(smem), "l"(gmem));
}
DI void cpcommit() { asm volatile("cp.async.commit_group;\n"); }
template <int N> DI void cpwait() { asm volatile("cp.async.wait_group %0;\n" :: "n"(N)); }

// One 32-k slab of MMAs. Ab = warp's fragment region; chunk layout:
//   elem(row r, k) at [((k>>2)*4 + ((r>>4)&1)*2 + ((r>>3)&1))*32 + (r&7)*4 + (k&3)]
// Wb = packed slab base; kqbase = (global k offset)>>2 for this slab.
DI void mma_slab(float (*acc)[16][4], const unsigned* __restrict__ Ab,
                 const unsigned* __restrict__ Wb, int lane, int kqbase) {
#pragma unroll
    for (int ks = 0; ks < 4; ks++) {
        unsigned a[2][4];
#pragma unroll
        for (int mi = 0; mi < 2; mi++) {
            int c0 = (kqbase + ks * 2) * 4 + mi * 2;
            a[mi][0] = Ab[(c0 + 0) * 32 + lane];
            a[mi][1] = Ab[(c0 + 1) * 32 + lane];
            a[mi][2] = Ab[(c0 + 4) * 32 + lane];
            a[mi][3] = Ab[(c0 + 5) * 32 + lane];
        }
        const uint4* bb = (const uint4*)(Wb + (ks * 32 + lane) * 36);
#pragma unroll
        for (int jj = 0; jj < 8; jj++) {
            uint4 b = bb[jj];
            mma8(acc[0][2 * jj],     a[0][0], a[0][1], a[0][2], a[0][3], b.x, b.y);
            mma8(acc[1][2 * jj],     a[1][0], a[1][1], a[1][2], a[1][3], b.x, b.y);
            mma8(acc[0][2 * jj + 1], a[0][0], a[0][1], a[0][2], a[0][3], b.z, b.w);
            mma8(acc[1][2 * jj + 1], a[1][0], a[1][1], a[1][2], a[1][3], b.z, b.w);
        }
    }
}

// ---------------------------------------------------------------------------
// prep: Wfp = W_p@W1a, Wfv = W_v@W1b, biasF = b@W1x  (fp32). grid 16 x 256.
// ---------------------------------------------------------------------------
__global__ __launch_bounds__(256) void prep_kernel(
    const float* __restrict__ Wp, const float* __restrict__ bp,
    const float* __restrict__ Wv, const float* __restrict__ bv,
    const float* __restrict__ W1) {
    __shared__ float Wc_s[32 * 128];
    __shared__ float Wr_s[16 * 128];
    int cb = blockIdx.x;
    int isv = cb >= 8, rb = (cb & 7) * 16;
    const float* Wx  = isv ? Wv : Wp;
    const float* W1x = W1 + (isv ? 128 * 128 : 0);
    float* outW = isv ? g_Wfv : g_Wfp;
    int t = threadIdx.x;
    for (int i = t; i < 16 * 128; i += 256)
        Wr_s[i] = Wx[(rb + (i >> 7)) * 128 + (i & 127)];
    float acc[8];
#pragma unroll
    for (int ii = 0; ii < 8; ii++) acc[ii] = 0.f;
    int j = t & 127, ih = (t >> 7) * 8;
    for (int kc = 0; kc < 4; kc++) {
        __syncthreads();
        for (int i = t; i < 32 * 128; i += 256)
            Wc_s[i] = W1x[(kc * 32 + (i >> 7)) * 128 + (i & 127)];
        __syncthreads();
        for (int k = 0; k < 32; k++) {
            float b = Wc_s[k * 128 + j];
#pragma unroll
            for (int ii = 0; ii < 8; ii++)
                acc[ii] += Wr_s[(ih + ii) * 128 + kc * 32 + k] * b;
        }
    }
#pragma unroll
    for (int ii = 0; ii < 8; ii++) outW[(rb + ih + ii) * 128 + j] = acc[ii];
    if ((cb & 7) == 0 && t < 128) {
        const float* bx = isv ? bv : bp;
        float s = 0.f;
        for (int k = 0; k < 128; k++) s += bx[k] * W1x[k * 128 + t];
        g_biasF[isv * 128 + t] = s;
    }
}

// ---------------------------------------------------------------------------
// pack: tf32 fragment-order packing of all B operands. grid 28 x 128.
// dst[(ks*32+lane)*36 + 2j + r] = tf32(src[(ks*8 + t4 + 4r)*128 + 8j + gid])
// ---------------------------------------------------------------------------
__global__ __launch_bounds__(128) void pack_kernel(
    const float* __restrict__ W1, const float* __restrict__ W2,
    const float* __restrict__ Wp, const float* __restrict__ Wv) {
    int sid = blockIdx.x;
    const float* src;
    unsigned* dst;
    if      (sid < 8)  { src = W1 + (256 + sid * 32) * 128;     dst = g_W1f  + sid * 4608; }
    else if (sid < 12) { src = W2 + (sid - 8) * 32 * 128;       dst = g_W2f  + (sid - 8) * 4608; }
    else if (sid < 16) { src = Wp + (sid - 12) * 32 * 128;      dst = g_Wpf  + (sid - 12) * 4608; }
    else if (sid < 20) { src = g_Wfp + (sid - 16) * 32 * 128;   dst = g_Wfpf + (sid - 16) * 4608; }
    else if (sid < 24) { src = Wv + (sid - 20) * 32 * 128;      dst = g_Wvf  + (sid - 20) * 4608; }
    else               { src = g_Wfv + (sid - 24) * 32 * 128;   dst = g_Wfvf + (sid - 24) * 4608; }
    int t = threadIdx.x, lane = t & 31, ks = t >> 5;
    int gid = lane >> 2, t4 = lane & 3;
#pragma unroll
    for (int j = 0; j < 16; j++)
#pragma unroll
        for (int r = 0; r < 2; r++)
            dst[(ks * 32 + lane) * 36 + 2 * j + r] =
                f2tf(src[(ks * 8 + t4 + r * 4) * 128 + j * 8 + gid]);
}

// ---------------------------------------------------------------------------
// pv: p & P1 (price) or v & V1 (liquid) in one pass. grid 128 x 256.
// warps 0-3: weight pack 0 (p/v), warps 4-7: pack 1 (P1/V1); rowgrp = w&3.
// smem: W_s 9216u | A_f 4096u | bias 256f = 54272 B
// ---------------------------------------------------------------------------
__global__ __launch_bounds__(256) void pv_kernel(
    const float* __restrict__ price, const float* __restrict__ liquid,
    const float* __restrict__ bp, const float* __restrict__ bv) {
    extern __shared__ float smpv[];
    unsigned* W_s    = (unsigned*)smpv;
    unsigned* A_f    = (unsigned*)smpv + 9216;
    float*    bias_s = smpv + 13312;

    int cb = blockIdx.x;
    int isv = cb >= 64, rb = (cb & 63) * 128;
    const float* in = (isv ? liquid : price) + (size_t)rb * 128;
    const unsigned* packA = isv ? g_Wvf  : g_Wpf;
    const unsigned* packB = isv ? g_Wfvf : g_Wfpf;
    float* outA = (isv ? g_v  : g_p)  + (size_t)rb * 128;
    float* outB = (isv ? g_V1 : g_P1) + (size_t)rb * 128;

    int t = threadIdx.x, w = t >> 5, lane = t & 31;
    int gid = lane >> 2, t4 = lane & 3;
    if (t < 128) bias_s[t] = isv ? bv[t] : bp[t];
    else         bias_s[t] = g_biasF[isv * 128 + (t - 128)];

    uint32_t Wsa = (uint32_t)__cvta_generic_to_shared(W_s);
    int sub  = ((t & 31) >> 4) * 2 + ((t & 15) >> 3);
    int gid4 = (t & 7) * 4;
    int bgrp = (t >> 5) * 1024;   // builder region (t<128 only)
    int rowgrp = w & 3, pk = w >> 2;

    float acc[2][16][4];
#pragma unroll
    for (int mi = 0; mi < 2; mi++)
#pragma unroll
        for (int j = 0; j < 16; j++)
#pragma unroll
            for (int e = 0; e < 4; e++) acc[mi][j][e] = 0.f;

    for (int s = 0; s < 4; s++) {
        if (s) __syncthreads();
        for (int i = t; i < 2304; i += 256) {
            const void* src = (i < 1152)
                ? (const void*)((const uint4*)(packA + s * 4608) + i)
                : (const void*)((const uint4*)(packB + s * 4608) + (i - 1152));
            cp16(Wsa + i * 16, src);
        }
        cpcommit();
        if (t < 128) {
            const float4* row = (const float4*)(in + (size_t)t * 128 + s * 32);
#pragma unroll
            for (int g = 0; g < 8; g++) {
                float4 a = row[g];
                uint4 o = { f2tf(a.x), f2tf(a.y), f2tf(a.z), f2tf(a.w) };
                *(uint4*)&A_f[bgrp + (g * 4 + sub) * 32 + gid4] = o;
            }
        }
        cpwait<0>();
        __syncthreads();
        mma_slab(acc, A_f + rowgrp * 1024, W_s + pk * 4608, lane, 0);
    }
    float* outX = pk ? outB : outA;
#pragma unroll
    for (int mi = 0; mi < 2; mi++) {
        int r0 = rowgrp * 32 + mi * 16 + gid;
#pragma unroll
        for (int j = 0; j < 16; j++) {
            int c = j * 8 + 2 * t4;
            float b0 = bias_s[pk * 128 + c], b1 = bias_s[pk * 128 + c + 1];
            *(float2*)&outX[(size_t)r0 * 128 + c] =
                make_float2(acc[mi][j][0] + b0, acc[mi][j][1] + b1);
            *(float2*)&outX[(size_t)(r0 + 8) * 128 + c] =
                make_float2(acc[mi][j][2] + b0, acc[mi][j][3] + b1);
        }
    }
}

// ---------------------------------------------------------------------------
// main: one CTA per (bt, 4-n block) = 128 pairs x 128 cols. 128 thr, 4 warps.
// smem floats: Wbuf 2x4608u @0 | b1 @9216 | b2 @9344 | alias @9472:
//   phase1: v 32x132, V1 32x132, A_f 4096u, p 4x132, P1 4x132
//   phase2: h_f 16384u (tf32 fragment order, 4096u per warp)
// total 103424 B -> 2 CTAs/SM
// ---------------------------------------------------------------------------
__global__ __launch_bounds__(128) void pair_main_kernel(
    const float* __restrict__ b1v, const float* __restrict__ b2v,
    float* __restrict__ out) {
    extern __shared__ float sm[];
    unsigned* Wbuf = (unsigned*)sm;
    float* b1_s = sm + 9216;
    float* b2_s = sm + 9344;
    float* AL   = sm + 9472;
    float*    v_s  = AL;
    float*    V1_s = AL + 4224;
    unsigned* A_f  = (unsigned*)(AL + 8448);
    float*    p_s  = AL + 12544;
    float*    P1_s = AL + 13072;
    unsigned* h_f  = (unsigned*)AL;   // phase 2 alias

    const int bt = blockIdx.x >> 3, pb = blockIdx.x & 7;
    const int t = threadIdx.x, w = t >> 5, lane = t & 31;
    const int gid = lane >> 2, t4 = lane & 3;
    uint32_t Wba = (uint32_t)__cvta_generic_to_shared(Wbuf);

    // prefetch W1 slab 0 -> buf 0
    for (int i = t; i < 1152; i += 128) cp16(Wba + i * 16, (const uint4*)g_W1f + i);
    cpcommit();

    {   // tile loads
        const float4* vg  = (const float4*)(g_v  + (size_t)bt * 4096);
        const float4* V1g = (const float4*)(g_V1 + (size_t)bt * 4096);
        for (int i = t; i < 1024; i += 128) {
            int m = i >> 5, k4 = (i & 31) * 4;
            *(float4*)&v_s [m * 132 + k4] = vg[i];
            *(float4*)&V1_s[m * 132 + k4] = V1g[i];
        }
        const float4* pg  = (const float4*)(g_p  + (size_t)(bt * 32 + pb * 4) * 128);
        const float4* P1g = (const float4*)(g_P1 + (size_t)(bt * 32 + pb * 4) * 128);
        {
            int n = t >> 5, k4 = (t & 31) * 4;
            *(float4*)&p_s [n * 132 + k4] = pg[t];
            *(float4*)&P1_s[n * 132 + k4] = P1g[t];
        }
        b1_s[t] = b1v[t];
        b2_s[t] = b2v[t];
    }
    __syncthreads();

    float acc[2][16][4];
#pragma unroll
    for (int mi = 0; mi < 2; mi++)
#pragma unroll
        for (int j = 0; j < 16; j++)
#pragma unroll
            for (int e = 0; e < 4; e++) acc[mi][j][e] = 0.f;

    const int sub  = ((lane >> 4) & 1) * 2 + ((lane >> 3) & 1);
    const int gid4 = (lane & 7) * 4;

    // ---------------- GEMM1: K=256 (prod slabs 0-3, absdiff 4-7) -----------
    for (int s = 0; s < 8; s++) {
        if (s) __syncthreads();
        if (s < 7) {   // prefetch next W1 slab
            for (int i = t; i < 1152; i += 128)
                cp16(Wba + ((s + 1) & 1) * 18432 + i * 16,
                     (const uint4*)(g_W1f + (s + 1) * 4608) + i);
        } else {       // prefetch W2 slab 0 -> buf 0
            for (int i = t; i < 1152; i += 128)
                cp16(Wba + i * 16, (const uint4*)g_W2f + i);
        }
        cpcommit();
        {   // build A fragments: thread t = pair-row t (n = w, m = lane)
            int kb0 = (s & 3) * 32;
            const float4* pr = (const float4*)(p_s + w * 132 + kb0);
            const float4* vr = (const float4*)(v_s + lane * 132 + kb0);
            if (s < 4) {
#pragma unroll
                for (int g = 0; g < 8; g++) {
                    float4 a = pr[g], b = vr[g];
                    uint4 o = { f2tf(a.x * b.x), f2tf(a.y * b.y),
                                f2tf(a.z * b.z), f2tf(a.w * b.w) };
                    *(uint4*)&A_f[w * 1024 + (g * 4 + sub) * 32 + gid4] = o;
                }
            } else {
#pragma unroll
                for (int g = 0; g < 8; g++) {
                    float4 a = pr[g], b = vr[g];
                    uint4 o = { f2tf(fabsf(a.x - b.x)), f2tf(fabsf(a.y - b.y)),
                                f2tf(fabsf(a.z - b.z)), f2tf(fabsf(a.w - b.w)) };
                    *(uint4*)&A_f[w * 1024 + (g * 4 + sub) * 32 + gid4] = o;
                }
            }
        }
        cpwait<1>();
        __syncthreads();
        mma_slab(acc, A_f + w * 1024, Wbuf + (s & 1) * 4608, lane, 0);
    }

    // ------------- epilogue 1: + P1[w] + V1[m] + b1, SiLU ------------------
#pragma unroll
    for (int mi = 0; mi < 2; mi++) {
        int m0 = mi * 16 + gid, m1 = m0 + 8;
#pragma unroll
        for (int j = 0; j < 16; j++) {
            int c0 = j * 8 + 2 * t4;
#pragma unroll
            for (int e = 0; e < 4; e++) {
                int mm = (e < 2) ? m0 : m1;
                int cc = c0 + (e & 1);
                float x = acc[mi][j][e] + P1_s[w * 132 + cc] + V1_s[mm * 132 + cc] + b1_s[cc];
                acc[mi][j][e] = x / (1.f + __expf(-x));
            }
        }
    }
    __syncthreads();   // done reading phase-1 alias buffers

    // stage h in GEMM2 fragment order, pre-converted to tf32
#pragma unroll
    for (int mi = 0; mi < 2; mi++) {
#pragma unroll
        for (int j = 0; j < 16; j++) {
            int kq = j * 2 + (t4 >> 1);
            int base = w * 4096 + kq * 128 + gid * 4 + 2 * (t4 & 1);
            uint2 lo = { f2tf(acc[mi][j][0]), f2tf(acc[mi][j][1]) };
            uint2 hi = { f2tf(acc[mi][j][2]), f2tf(acc[mi][j][3]) };
            *(uint2*)&h_f[base + (mi * 2 + 0) * 32] = lo;
            *(uint2*)&h_f[base + (mi * 2 + 1) * 32] = hi;
        }
    }
#pragma unroll
    for (int mi = 0; mi < 2; mi++)
#pragma unroll
        for (int j = 0; j < 16; j++)
#pragma unroll
            for (int e = 0; e < 4; e++) acc[mi][j][e] = 0.f;
    __syncthreads();

    // ---------------- GEMM2: h(128x128) @ W2 -------------------------------
    for (int s = 0; s < 4; s++) {
        if (s) __syncthreads();
        if (s < 3) {
            for (int i = t; i < 1152; i += 128)
                cp16(Wba + ((s + 1) & 1) * 18432 + i * 16,
                     (const uint4*)(g_W2f + (s + 1) * 4608) + i);
            cpcommit();
            cpwait<1>();
        } else {
            cpwait<0>();
        }
        __syncthreads();
        mma_slab(acc, h_f + w * 4096, Wbuf + (s & 1) * 4608, lane, s * 8);
    }

    // ------------- epilogue 2: + b2, direct sector-aligned STG.64 ----------
    const size_t ob = (size_t)blockIdx.x * 16384;
#pragma unroll
    for (int mi = 0; mi < 2; mi++) {
        float* o0 = out + ob + (size_t)(w * 32 + mi * 16 + gid) * 128;
        float* o1 = o0 + 8 * 128;
#pragma unroll
        for (int j = 0; j < 16; j++) {
            int c = j * 8 + 2 * t4;
            *(float2*)&o0[c] = make_float2(acc[mi][j][0] + b2_s[c],
                                           acc[mi][j][1] + b2_s[c + 1]);
            *(float2*)&o1[c] = make_float2(acc[mi][j][2] + b2_s[c],
                                           acc[mi][j][3] + b2_s[c + 1]);
        }
    }
}

// ---------------------------------------------------------------------------
extern "C" void kernel_launch(void* const* d_in, const int* in_sizes, int n_in,
                              void* d_out, int out_size) {
    const float* price  = (const float*)d_in[0];
    const float* liquid = (const float*)d_in[1];
    const float* W_p    = (const float*)d_in[2];
    const float* b_p    = (const float*)d_in[3];
    const float* W_v    = (const float*)d_in[4];
    const float* b_v    = (const float*)d_in[5];
    const float* W1     = (const float*)d_in[6];
    const float* b1     = (const float*)d_in[7];
    const float* W2     = (const float*)d_in[8];
    const float* b2     = (const float*)d_in[9];
    float* out = (float*)d_out;

    cudaFuncSetAttribute(pv_kernel,
                         cudaFuncAttributeMaxDynamicSharedMemorySize, 55296);
    cudaFuncSetAttribute(pair_main_kernel,
                         cudaFuncAttributeMaxDynamicSharedMemorySize, 104448);

    prep_kernel<<<16, 256>>>(W_p, b_p, W_v, b_v, W1);
    pack_kernel<<<28, 128>>>(W1, W2, W_p, W_v);
    pv_kernel<<<128, 256, 54272>>>(price, liquid, b_p, b_v);
    pair_main_kernel<<<2048, 128, 103424>>>(b1, b2, out);
}

// round 4
// speedup vs baseline: 2.6469x; 1.3486x over previous
#include <cuda_runtime.h>
#include <cstdint>

#define DI __device__ __forceinline__

// ---------------- scratch globals (allocation-free rule) -------------------
__device__ float g_p [8192 * 128];
__device__ float g_v [8192 * 128];
__device__ float g_P1[8192 * 128];
__device__ float g_V1[8192 * 128];
__device__ float g_Wfp[128 * 128];     // W_p @ W1a
__device__ float g_Wfv[128 * 128];     // W_v @ W1b
__device__ float g_biasF[2 * 128];     // b_p@W1a , b_v@W1b

// tf32 fragment-packed weights: slab = [kstep(4) x lane(32)] x 36 (stride pad)
__device__ __align__(16) unsigned g_W1f [8 * 4608];   // W1c|W1d (rows 256..511)
__device__ __align__(16) unsigned g_W2f [4 * 4608];
__device__ __align__(16) unsigned g_Wpf [4 * 4608];
__device__ __align__(16) unsigned g_Wfpf[4 * 4608];
__device__ __align__(16) unsigned g_Wvf [4 * 4608];
__device__ __align__(16) unsigned g_Wfvf[4 * 4608];

DI unsigned f2tf(float x) {
    unsigned r;
    asm("cvt.rna.tf32.f32 %0, %1;" : "=r"(r) : "f"(x));
    return r;
}
DI void mma8(float* c, unsigned a0, unsigned a1, unsigned a2, unsigned a3,
             unsigned b0, unsigned b1) {
    asm volatile(
        "mma.sync.aligned.m16n8k8.row.col.f32.tf32.tf32.f32 "
        "{%0,%1,%2,%3},{%4,%5,%6,%7},{%8,%9},{%0,%1,%2,%3};\n"
        : "+f"(c[0]), "+f"(c[1]), "+f"(c[2]), "+f"(c[3])
        : "r"(a0), "r"(a1), "r"(a2), "r"(a3), "r"(b0), "r"(b1));
}
DI void cp16(uint32_t smem, const void* gmem) {
    asm volatile("cp.async.cg.shared.global [%0], [%1], 16;\n" :: "r"(smem), "l"(gmem));
}
DI void cpcommit() { asm volatile("cp.async.commit_group;\n"); }
template <int N> DI void cpwait() { asm volatile("cp.async.wait_group %0;\n" :: "n"(N)); }

// MMA over one 32-k slab, A fragments from smem (chunk layout).
DI void mma_slab(float (*acc)[16][4], const unsigned* __restrict__ Ab,
                 const unsigned* __restrict__ Wb, int lane, int kqbase) {
#pragma unroll
    for (int ks = 0; ks < 4; ks++) {
        unsigned a[2][4];
#pragma unroll
        for (int mi = 0; mi < 2; mi++) {
            int c0 = (kqbase + ks * 2) * 4 + mi * 2;
            a[mi][0] = Ab[(c0 + 0) * 32 + lane];
            a[mi][1] = Ab[(c0 + 1) * 32 + lane];
            a[mi][2] = Ab[(c0 + 4) * 32 + lane];
            a[mi][3] = Ab[(c0 + 5) * 32 + lane];
        }
        const uint4* bb = (const uint4*)(Wb + (ks * 32 + lane) * 36);
#pragma unroll
        for (int jj = 0; jj < 8; jj++) {
            uint4 b = bb[jj];
            mma8(acc[0][2 * jj],     a[0][0], a[0][1], a[0][2], a[0][3], b.x, b.y);
            mma8(acc[1][2 * jj],     a[1][0], a[1][1], a[1][2], a[1][3], b.x, b.y);
            mma8(acc[0][2 * jj + 1], a[0][0], a[0][1], a[0][2], a[0][3], b.z, b.w);
            mma8(acc[1][2 * jj + 1], a[1][0], a[1][1], a[1][2], a[1][3], b.z, b.w);
        }
    }
}

// MMA over one 32-k slab, A fragments in registers.
DI void mma_slab_r(float (*acc)[16][4], const unsigned (*af)[2][4],
                   const unsigned* __restrict__ Wb, int lane) {
#pragma unroll
    for (int ks = 0; ks < 4; ks++) {
        const uint4* bb = (const uint4*)(Wb + (ks * 32 + lane) * 36);
#pragma unroll
        for (int jj = 0; jj < 8; jj++) {
            uint4 b = bb[jj];
            mma8(acc[0][2 * jj],     af[ks][0][0], af[ks][0][1], af[ks][0][2], af[ks][0][3], b.x, b.y);
            mma8(acc[1][2 * jj],     af[ks][1][0], af[ks][1][1], af[ks][1][2], af[ks][1][3], b.x, b.y);
            mma8(acc[0][2 * jj + 1], af[ks][0][0], af[ks][0][1], af[ks][0][2], af[ks][0][3], b.z, b.w);
            mma8(acc[1][2 * jj + 1], af[ks][1][0], af[ks][1][1], af[ks][1][2], af[ks][1][3], b.z, b.w);
        }
    }
}

// ---------------------------------------------------------------------------
// prep: Wfp = W_p@W1a, Wfv = W_v@W1b, biasF = b@W1x  (fp32). grid 16 x 256.
// ---------------------------------------------------------------------------
__global__ __launch_bounds__(256) void prep_kernel(
    const float* __restrict__ Wp, const float* __restrict__ bp,
    const float* __restrict__ Wv, const float* __restrict__ bv,
    const float* __restrict__ W1) {
    __shared__ float Wc_s[32 * 128];
    __shared__ float Wr_s[16 * 128];
    int cb = blockIdx.x;
    int isv = cb >= 8, rb = (cb & 7) * 16;
    const float* Wx  = isv ? Wv : Wp;
    const float* W1x = W1 + (isv ? 128 * 128 : 0);
    float* outW = isv ? g_Wfv : g_Wfp;
    int t = threadIdx.x;
    for (int i = t; i < 16 * 128; i += 256)
        Wr_s[i] = Wx[(rb + (i >> 7)) * 128 + (i & 127)];
    float acc[8];
#pragma unroll
    for (int ii = 0; ii < 8; ii++) acc[ii] = 0.f;
    int j = t & 127, ih = (t >> 7) * 8;
    for (int kc = 0; kc < 4; kc++) {
        __syncthreads();
        for (int i = t; i < 32 * 128; i += 256)
            Wc_s[i] = W1x[(kc * 32 + (i >> 7)) * 128 + (i & 127)];
        __syncthreads();
        for (int k = 0; k < 32; k++) {
            float b = Wc_s[k * 128 + j];
#pragma unroll
            for (int ii = 0; ii < 8; ii++)
                acc[ii] += Wr_s[(ih + ii) * 128 + kc * 32 + k] * b;
        }
    }
#pragma unroll
    for (int ii = 0; ii < 8; ii++) outW[(rb + ih + ii) * 128 + j] = acc[ii];
    if ((cb & 7) == 0 && t < 128) {
        const float* bx = isv ? bv : bp;
        float s = 0.f;
        for (int k = 0; k < 128; k++) s += bx[k] * W1x[k * 128 + t];
        g_biasF[isv * 128 + t] = s;
    }
}

// ---------------------------------------------------------------------------
// pack: tf32 fragment-order packing of all B operands. grid 28 x 128.
// ---------------------------------------------------------------------------
__global__ __launch_bounds__(128) void pack_kernel(
    const float* __restrict__ W1, const float* __restrict__ W2,
    const float* __restrict__ Wp, const float* __restrict__ Wv) {
    int sid = blockIdx.x;
    const float* src;
    unsigned* dst;
    if      (sid < 8)  { src = W1 + (256 + sid * 32) * 128;     dst = g_W1f  + sid * 4608; }
    else if (sid < 12) { src = W2 + (sid - 8) * 32 * 128;       dst = g_W2f  + (sid - 8) * 4608; }
    else if (sid < 16) { src = Wp + (sid - 12) * 32 * 128;      dst = g_Wpf  + (sid - 12) * 4608; }
    else if (sid < 20) { src = g_Wfp + (sid - 16) * 32 * 128;   dst = g_Wfpf + (sid - 16) * 4608; }
    else if (sid < 24) { src = Wv + (sid - 20) * 32 * 128;      dst = g_Wvf  + (sid - 20) * 4608; }
    else               { src = g_Wfv + (sid - 24) * 32 * 128;   dst = g_Wfvf + (sid - 24) * 4608; }
    int t = threadIdx.x, lane = t & 31, ks = t >> 5;
    int gid = lane >> 2, t4 = lane & 3;
#pragma unroll
    for (int j = 0; j < 16; j++)
#pragma unroll
        for (int r = 0; r < 2; r++)
            dst[(ks * 32 + lane) * 36 + 2 * j + r] =
                f2tf(src[(ks * 8 + t4 + r * 4) * 128 + j * 8 + gid]);
}

// ---------------------------------------------------------------------------
// pv: p & P1 (price) or v & V1 (liquid) in one pass. grid 128 x 256.
// ---------------------------------------------------------------------------
__global__ __launch_bounds__(256) void pv_kernel(
    const float* __restrict__ price, const float* __restrict__ liquid,
    const float* __restrict__ bp, const float* __restrict__ bv) {
    extern __shared__ float smpv[];
    unsigned* W_s    = (unsigned*)smpv;
    unsigned* A_f    = (unsigned*)smpv + 9216;
    float*    bias_s = smpv + 13312;

    int cb = blockIdx.x;
    int isv = cb >= 64, rb = (cb & 63) * 128;
    const float* in = (isv ? liquid : price) + (size_t)rb * 128;
    const unsigned* packA = isv ? g_Wvf  : g_Wpf;
    const unsigned* packB = isv ? g_Wfvf : g_Wfpf;
    float* outA = (isv ? g_v  : g_p)  + (size_t)rb * 128;
    float* outB = (isv ? g_V1 : g_P1) + (size_t)rb * 128;

    int t = threadIdx.x, w = t >> 5, lane = t & 31;
    int gid = lane >> 2, t4 = lane & 3;
    if (t < 128) bias_s[t] = isv ? bv[t] : bp[t];
    else         bias_s[t] = g_biasF[isv * 128 + (t - 128)];

    uint32_t Wsa = (uint32_t)__cvta_generic_to_shared(W_s);
    int sub  = ((t & 31) >> 4) * 2 + ((t & 15) >> 3);
    int gid4 = (t & 7) * 4;
    int bgrp = (t >> 5) * 1024;
    int rowgrp = w & 3, pk = w >> 2;

    float acc[2][16][4];
#pragma unroll
    for (int mi = 0; mi < 2; mi++)
#pragma unroll
        for (int j = 0; j < 16; j++)
#pragma unroll
            for (int e = 0; e < 4; e++) acc[mi][j][e] = 0.f;

    for (int s = 0; s < 4; s++) {
        if (s) __syncthreads();
        for (int i = t; i < 2304; i += 256) {
            const void* src = (i < 1152)
                ? (const void*)((const uint4*)(packA + s * 4608) + i)
                : (const void*)((const uint4*)(packB + s * 4608) + (i - 1152));
            cp16(Wsa + i * 16, src);
        }
        cpcommit();
        if (t < 128) {
            const float4* row = (const float4*)(in + (size_t)t * 128 + s * 32);
#pragma unroll
            for (int g = 0; g < 8; g++) {
                float4 a = row[g];
                uint4 o = { f2tf(a.x), f2tf(a.y), f2tf(a.z), f2tf(a.w) };
                *(uint4*)&A_f[bgrp + (g * 4 + sub) * 32 + gid4] = o;
            }
        }
        cpwait<0>();
        __syncthreads();
        mma_slab(acc, A_f + rowgrp * 1024, W_s + pk * 4608, lane, 0);
    }
    float* outX = pk ? outB : outA;
#pragma unroll
    for (int mi = 0; mi < 2; mi++) {
        int r0 = rowgrp * 32 + mi * 16 + gid;
#pragma unroll
        for (int j = 0; j < 16; j++) {
            int c = j * 8 + 2 * t4;
            float b0 = bias_s[pk * 128 + c], b1 = bias_s[pk * 128 + c + 1];
            *(float2*)&outX[(size_t)r0 * 128 + c] =
                make_float2(acc[mi][j][0] + b0, acc[mi][j][1] + b1);
            *(float2*)&outX[(size_t)(r0 + 8) * 128 + c] =
                make_float2(acc[mi][j][2] + b0, acc[mi][j][3] + b1);
        }
    }
}

// ---------------------------------------------------------------------------
// main: one CTA per (bt, 4-n block) = 128 pairs x 128 cols. 128 thr, 4 warps.
// A fragments for GEMM1 built DIRECTLY in registers (n fixed per warp):
//   frag(row m, k) = p_w[k]*v_m[k]  or  |p_w[k]-v_m[k]|
// smem floats: Wbuf 2x4608u @0 | b1 @9216 | b2 @9344 | alias @9472:
//   phase1: v 32x132, V1 32x132, p 4x132, P1 4x132   phase2: h_f 16384u
// total 103424 B -> 2 CTAs/SM
// ---------------------------------------------------------------------------
__global__ __launch_bounds__(128) void pair_main_kernel(
    const float* __restrict__ b1v, const float* __restrict__ b2v,
    float* __restrict__ out) {
    extern __shared__ float sm[];
    unsigned* Wbuf = (unsigned*)sm;
    float* b1_s = sm + 9216;
    float* b2_s = sm + 9344;
    float* AL   = sm + 9472;
    float*    v_s  = AL;            // 32 x 132
    float*    V1_s = AL + 4224;     // 32 x 132
    float*    p_s  = AL + 8448;     // 4 x 132
    float*    P1_s = AL + 8976;     // 4 x 132
    unsigned* h_f  = (unsigned*)AL; // phase 2 alias (16384 u32)

    const int bt = blockIdx.x >> 3, pb = blockIdx.x & 7;
    const int t = threadIdx.x, w = t >> 5, lane = t & 31;
    const int gid = lane >> 2, t4 = lane & 3;
    uint32_t Wba = (uint32_t)__cvta_generic_to_shared(Wbuf);

    // prefetch W1 slab 0 -> buf 0
    for (int i = t; i < 1152; i += 128) cp16(Wba + i * 16, (const uint4*)g_W1f + i);
    cpcommit();

    {   // tile loads
        const float4* vg  = (const float4*)(g_v  + (size_t)bt * 4096);
        const float4* V1g = (const float4*)(g_V1 + (size_t)bt * 4096);
        for (int i = t; i < 1024; i += 128) {
            int m = i >> 5, k4 = (i & 31) * 4;
            *(float4*)&v_s [m * 132 + k4] = vg[i];
            *(float4*)&V1_s[m * 132 + k4] = V1g[i];
        }
        const float4* pg  = (const float4*)(g_p  + (size_t)(bt * 32 + pb * 4) * 128);
        const float4* P1g = (const float4*)(g_P1 + (size_t)(bt * 32 + pb * 4) * 128);
        {
            int n = t >> 5, k4 = (t & 31) * 4;
            *(float4*)&p_s [n * 132 + k4] = pg[t];
            *(float4*)&P1_s[n * 132 + k4] = P1g[t];
        }
        b1_s[t] = b1v[t];
        b2_s[t] = b2v[t];
    }

    float acc[2][16][4];
#pragma unroll
    for (int mi = 0; mi < 2; mi++)
#pragma unroll
        for (int j = 0; j < 16; j++)
#pragma unroll
            for (int e = 0; e < 4; e++) acc[mi][j][e] = 0.f;

    // ---------------- GEMM1: K=256 (prod slabs 0-3, absdiff 4-7) -----------
    // single-barrier cp.async ring: prefetch issued AFTER the barrier.
#pragma unroll 1
    for (int s = 0; s < 8; s++) {
        cpwait<0>();
        __syncthreads();
        {   // prefetch next slab (W2 slab 0 when s==7)
            const uint4* nxt = (s < 7) ? (const uint4*)(g_W1f + (s + 1) * 4608)
                                       : (const uint4*)g_W2f;
            uint32_t dst = Wba + (((s + 1) & 1) * 18432);
            for (int i = t; i < 1152; i += 128) cp16(dst + i * 16, nxt + i);
            cpcommit();
        }
        // build A fragments in registers
        unsigned af[4][2][4];
        {
            const int kb0 = (s & 3) * 32;
            const float* pw = p_s + w * 132 + kb0 + t4;
            const float* vv = v_s + gid * 132 + kb0 + t4;
#pragma unroll
            for (int ks = 0; ks < 4; ks++) {
                float pa = pw[ks * 8], pb = pw[ks * 8 + 4];
#pragma unroll
                for (int mi = 0; mi < 2; mi++) {
                    const float* vb = vv + mi * 2112;   // +16 rows
                    float v00 = vb[ks * 8];
                    float v10 = vb[1056 + ks * 8];      // +8 rows
                    float v01 = vb[ks * 8 + 4];
                    float v11 = vb[1056 + ks * 8 + 4];
                    if (s < 4) {
                        af[ks][mi][0] = f2tf(pa * v00);
                        af[ks][mi][1] = f2tf(pa * v10);
                        af[ks][mi][2] = f2tf(pb * v01);
                        af[ks][mi][3] = f2tf(pb * v11);
                    } else {
                        af[ks][mi][0] = f2tf(fabsf(pa - v00));
                        af[ks][mi][1] = f2tf(fabsf(pa - v10));
                        af[ks][mi][2] = f2tf(fabsf(pb - v01));
                        af[ks][mi][3] = f2tf(fabsf(pb - v11));
                    }
                }
            }
        }
        mma_slab_r(acc, af, Wbuf + (s & 1) * 4608, lane);
    }

    // ------------- epilogue 1: + P1[w] + V1[m] + b1, SiLU ------------------
#pragma unroll
    for (int mi = 0; mi < 2; mi++) {
        int m0 = mi * 16 + gid, m1 = m0 + 8;
#pragma unroll
        for (int j = 0; j < 16; j++) {
            int c0 = j * 8 + 2 * t4;
#pragma unroll
            for (int e = 0; e < 4; e++) {
                int mm = (e < 2) ? m0 : m1;
                int cc = c0 + (e & 1);
                float x = acc[mi][j][e] + P1_s[w * 132 + cc] + V1_s[mm * 132 + cc] + b1_s[cc];
                acc[mi][j][e] = x / (1.f + __expf(-x));
            }
        }
    }
    __syncthreads();   // done reading phase-1 alias buffers

    // stage h in GEMM2 fragment order, pre-converted to tf32
#pragma unroll
    for (int mi = 0; mi < 2; mi++) {
#pragma unroll
        for (int j = 0; j < 16; j++) {
            int kq = j * 2 + (t4 >> 1);
            int base = w * 4096 + kq * 128 + gid * 4 + 2 * (t4 & 1);
            uint2 lo = { f2tf(acc[mi][j][0]), f2tf(acc[mi][j][1]) };
            uint2 hi = { f2tf(acc[mi][j][2]), f2tf(acc[mi][j][3]) };
            *(uint2*)&h_f[base + (mi * 2 + 0) * 32] = lo;
            *(uint2*)&h_f[base + (mi * 2 + 1) * 32] = hi;
        }
    }
#pragma unroll
    for (int mi = 0; mi < 2; mi++)
#pragma unroll
        for (int j = 0; j < 16; j++)
#pragma unroll
            for (int e = 0; e < 4; e++) acc[mi][j][e] = 0.f;

    // ---------------- GEMM2: h(128x128) @ W2 -------------------------------
#pragma unroll 1
    for (int s2 = 0; s2 < 4; s2++) {
        cpwait<0>();
        __syncthreads();   // also publishes h_f on s2==0
        if (s2 < 3) {
            uint32_t dst = Wba + (((s2 + 1) & 1) * 18432);
            const uint4* nxt = (const uint4*)(g_W2f + (s2 + 1) * 4608);
            for (int i = t; i < 1152; i += 128) cp16(dst + i * 16, nxt + i);
            cpcommit();
        }
        mma_slab(acc, h_f + w * 4096, Wbuf + (s2 & 1) * 4608, lane, s2 * 8);
    }

    // ------------- epilogue 2: + b2, direct sector-aligned stores ----------
    const size_t ob = (size_t)blockIdx.x * 16384;
#pragma unroll
    for (int mi = 0; mi < 2; mi++) {
        float* o0 = out + ob + (size_t)(w * 32 + mi * 16 + gid) * 128;
        float* o1 = o0 + 8 * 128;
#pragma unroll
        for (int j = 0; j < 16; j++) {
            int c = j * 8 + 2 * t4;
            *(float2*)&o0[c] = make_float2(acc[mi][j][0] + b2_s[c],
                                           acc[mi][j][1] + b2_s[c + 1]);
            *(float2*)&o1[c] = make_float2(acc[mi][j][2] + b2_s[c],
                                           acc[mi][j][3] + b2_s[c + 1]);
        }
    }
}

// ---------------------------------------------------------------------------
extern "C" void kernel_launch(void* const* d_in, const int* in_sizes, int n_in,
                              void* d_out, int out_size) {
    const float* price  = (const float*)d_in[0];
    const float* liquid = (const float*)d_in[1];
    const float* W_p    = (const float*)d_in[2];
    const float* b_p    = (const float*)d_in[3];
    const float* W_v    = (const float*)d_in[4];
    const float* b_v    = (const float*)d_in[5];
    const float* W1     = (const float*)d_in[6];
    const float* b1     = (const float*)d_in[7];
    const float* W2     = (const float*)d_in[8];
    const float* b2     = (const float*)d_in[9];
    float* out = (float*)d_out;

    cudaFuncSetAttribute(pv_kernel,
                         cudaFuncAttributeMaxDynamicSharedMemorySize, 55296);
    cudaFuncSetAttribute(pair_main_kernel,
                         cudaFuncAttributeMaxDynamicSharedMemorySize, 104448);

    prep_kernel<<<16, 256>>>(W_p, b_p, W_v, b_v, W1);
    pack_kernel<<<28, 128>>>(W1, W2, W_p, W_v);
    pv_kernel<<<128, 256, 54272>>>(price, liquid, b_p, b_v);
    pair_main_kernel<<<2048, 128, 103424>>>(b1, b2, out);
}

// round 5
// speedup vs baseline: 2.6631x; 1.0061x over previous
#include <cuda_runtime.h>
#include <cstdint>

#define DI __device__ __forceinline__

// ---------------- scratch globals (allocation-free rule) -------------------
__device__ float g_p [8192 * 128];
__device__ float g_v [8192 * 128];
__device__ float g_P1[8192 * 128];
__device__ float g_V1[8192 * 128];
__device__ float g_Wfp[128 * 128];     // W_p @ W1a
__device__ float g_Wfv[128 * 128];     // W_v @ W1b
__device__ float g_biasF[2 * 128];     // b_p@W1a , b_v@W1b

// tf32 fragment-packed weights: slab = [kstep(4) x lane(32)] x 36 (stride pad)
__device__ __align__(16) unsigned g_W1f [8 * 4608];   // W1c|W1d (rows 256..511)
__device__ __align__(16) unsigned g_W2f [4 * 4608];
__device__ __align__(16) unsigned g_Wpf [4 * 4608];
__device__ __align__(16) unsigned g_Wfpf[4 * 4608];
__device__ __align__(16) unsigned g_Wvf [4 * 4608];
__device__ __align__(16) unsigned g_Wfvf[4 * 4608];

DI unsigned f2tf(float x) {
    unsigned r;
    asm("cvt.rna.tf32.f32 %0, %1;" : "=r"(r) : "f"(x));
    return r;
}
DI void mma8(float* c, unsigned a0, unsigned a1, unsigned a2, unsigned a3,
             unsigned b0, unsigned b1) {
    asm volatile(
        "mma.sync.aligned.m16n8k8.row.col.f32.tf32.tf32.f32 "
        "{%0,%1,%2,%3},{%4,%5,%6,%7},{%8,%9},{%0,%1,%2,%3};\n"
        : "+f"(c[0]), "+f"(c[1]), "+f"(c[2]), "+f"(c[3])
        : "r"(a0), "r"(a1), "r"(a2), "r"(a3), "r"(b0), "r"(b1));
}
DI void cp16(uint32_t smem, const void* gmem) {
    asm volatile("cp.async.cg.shared.global [%0], [%1], 16;\n" :: "r"(smem), "l"(gmem));
}
DI void cpcommit() { asm volatile("cp.async.commit_group;\n"); }
template <int N> DI void cpwait() { asm volatile("cp.async.wait_group %0;\n" :: "n"(N)); }

// MMA over one 32-k slab, A fragments from smem (chunk layout).
DI void mma_slab(float (*acc)[16][4], const unsigned* __restrict__ Ab,
                 const unsigned* __restrict__ Wb, int lane, int kqbase) {
#pragma unroll
    for (int ks = 0; ks < 4; ks++) {
        unsigned a[2][4];
#pragma unroll
        for (int mi = 0; mi < 2; mi++) {
            int c0 = (kqbase + ks * 2) * 4 + mi * 2;
            a[mi][0] = Ab[(c0 + 0) * 32 + lane];
            a[mi][1] = Ab[(c0 + 1) * 32 + lane];
            a[mi][2] = Ab[(c0 + 4) * 32 + lane];
            a[mi][3] = Ab[(c0 + 5) * 32 + lane];
        }
        const uint4* bb = (const uint4*)(Wb + (ks * 32 + lane) * 36);
#pragma unroll
        for (int jj = 0; jj < 8; jj++) {
            uint4 b = bb[jj];
            mma8(acc[0][2 * jj],     a[0][0], a[0][1], a[0][2], a[0][3], b.x, b.y);
            mma8(acc[1][2 * jj],     a[1][0], a[1][1], a[1][2], a[1][3], b.x, b.y);
            mma8(acc[0][2 * jj + 1], a[0][0], a[0][1], a[0][2], a[0][3], b.z, b.w);
            mma8(acc[1][2 * jj + 1], a[1][0], a[1][1], a[1][2], a[1][3], b.z, b.w);
        }
    }
}

// MMA over one 32-k slab, A fragments in registers.
DI void mma_slab_r(float (*acc)[16][4], const unsigned (*af)[2][4],
                   const unsigned* __restrict__ Wb, int lane) {
#pragma unroll
    for (int ks = 0; ks < 4; ks++) {
        const uint4* bb = (const uint4*)(Wb + (ks * 32 + lane) * 36);
#pragma unroll
        for (int jj = 0; jj < 8; jj++) {
            uint4 b = bb[jj];
            mma8(acc[0][2 * jj],     af[ks][0][0], af[ks][0][1], af[ks][0][2], af[ks][0][3], b.x, b.y);
            mma8(acc[1][2 * jj],     af[ks][1][0], af[ks][1][1], af[ks][1][2], af[ks][1][3], b.x, b.y);
            mma8(acc[0][2 * jj + 1], af[ks][0][0], af[ks][0][1], af[ks][0][2], af[ks][0][3], b.z, b.w);
            mma8(acc[1][2 * jj + 1], af[ks][1][0], af[ks][1][1], af[ks][1][2], af[ks][1][3], b.z, b.w);
        }
    }
}

// ---------------------------------------------------------------------------
// prep: Wfp = W_p@W1a, Wfv = W_v@W1b, biasF = b@W1x  (fp32). grid 16 x 256.
// ---------------------------------------------------------------------------
__global__ __launch_bounds__(256) void prep_kernel(
    const float* __restrict__ Wp, const float* __restrict__ bp,
    const float* __restrict__ Wv, const float* __restrict__ bv,
    const float* __restrict__ W1) {
    __shared__ float Wc_s[32 * 128];
    __shared__ float Wr_s[16 * 128];
    int cb = blockIdx.x;
    int isv = cb >= 8, rb = (cb & 7) * 16;
    const float* Wx  = isv ? Wv : Wp;
    const float* W1x = W1 + (isv ? 128 * 128 : 0);
    float* outW = isv ? g_Wfv : g_Wfp;
    int t = threadIdx.x;
    for (int i = t; i < 16 * 128; i += 256)
        Wr_s[i] = Wx[(rb + (i >> 7)) * 128 + (i & 127)];
    float acc[8];
#pragma unroll
    for (int ii = 0; ii < 8; ii++) acc[ii] = 0.f;
    int j = t & 127, ih = (t >> 7) * 8;
    for (int kc = 0; kc < 4; kc++) {
        __syncthreads();
        for (int i = t; i < 32 * 128; i += 256)
            Wc_s[i] = W1x[(kc * 32 + (i >> 7)) * 128 + (i & 127)];
        __syncthreads();
        for (int k = 0; k < 32; k++) {
            float b = Wc_s[k * 128 + j];
#pragma unroll
            for (int ii = 0; ii < 8; ii++)
                acc[ii] += Wr_s[(ih + ii) * 128 + kc * 32 + k] * b;
        }
    }
#pragma unroll
    for (int ii = 0; ii < 8; ii++) outW[(rb + ih + ii) * 128 + j] = acc[ii];
    if ((cb & 7) == 0 && t < 128) {
        const float* bx = isv ? bv : bp;
        float s = 0.f;
        for (int k = 0; k < 128; k++) s += bx[k] * W1x[k * 128 + t];
        g_biasF[isv * 128 + t] = s;
    }
}

// ---------------------------------------------------------------------------
// pack: tf32 fragment-order packing of all B operands. grid 28 x 128.
// ---------------------------------------------------------------------------
__global__ __launch_bounds__(128) void pack_kernel(
    const float* __restrict__ W1, const float* __restrict__ W2,
    const float* __restrict__ Wp, const float* __restrict__ Wv) {
    int sid = blockIdx.x;
    const float* src;
    unsigned* dst;
    if      (sid < 8)  { src = W1 + (256 + sid * 32) * 128;     dst = g_W1f  + sid * 4608; }
    else if (sid < 12) { src = W2 + (sid - 8) * 32 * 128;       dst = g_W2f  + (sid - 8) * 4608; }
    else if (sid < 16) { src = Wp + (sid - 12) * 32 * 128;      dst = g_Wpf  + (sid - 12) * 4608; }
    else if (sid < 20) { src = g_Wfp + (sid - 16) * 32 * 128;   dst = g_Wfpf + (sid - 16) * 4608; }
    else if (sid < 24) { src = Wv + (sid - 20) * 32 * 128;      dst = g_Wvf  + (sid - 20) * 4608; }
    else               { src = g_Wfv + (sid - 24) * 32 * 128;   dst = g_Wfvf + (sid - 24) * 4608; }
    int t = threadIdx.x, lane = t & 31, ks = t >> 5;
    int gid = lane >> 2, t4 = lane & 3;
#pragma unroll
    for (int j = 0; j < 16; j++)
#pragma unroll
        for (int r = 0; r < 2; r++)
            dst[(ks * 32 + lane) * 36 + 2 * j + r] =
                f2tf(src[(ks * 8 + t4 + r * 4) * 128 + j * 8 + gid]);
}

// ---------------------------------------------------------------------------
// pv: p & P1 (price) or v & V1 (liquid) in one pass. grid 128 x 256.
// ---------------------------------------------------------------------------
__global__ __launch_bounds__(256) void pv_kernel(
    const float* __restrict__ price, const float* __restrict__ liquid,
    const float* __restrict__ bp, const float* __restrict__ bv) {
    extern __shared__ float smpv[];
    unsigned* W_s    = (unsigned*)smpv;
    unsigned* A_f    = (unsigned*)smpv + 9216;
    float*    bias_s = smpv + 13312;

    int cb = blockIdx.x;
    int isv = cb >= 64, rb = (cb & 63) * 128;
    const float* in = (isv ? liquid : price) + (size_t)rb * 128;
    const unsigned* packA = isv ? g_Wvf  : g_Wpf;
    const unsigned* packB = isv ? g_Wfvf : g_Wfpf;
    float* outA = (isv ? g_v  : g_p)  + (size_t)rb * 128;
    float* outB = (isv ? g_V1 : g_P1) + (size_t)rb * 128;

    int t = threadIdx.x, w = t >> 5, lane = t & 31;
    int gid = lane >> 2, t4 = lane & 3;
    if (t < 128) bias_s[t] = isv ? bv[t] : bp[t];
    else         bias_s[t] = g_biasF[isv * 128 + (t - 128)];

    uint32_t Wsa = (uint32_t)__cvta_generic_to_shared(W_s);
    int sub  = ((t & 31) >> 4) * 2 + ((t & 15) >> 3);
    int gid4 = (t & 7) * 4;
    int bgrp = (t >> 5) * 1024;
    int rowgrp = w & 3, pk = w >> 2;

    float acc[2][16][4];
#pragma unroll
    for (int mi = 0; mi < 2; mi++)
#pragma unroll
        for (int j = 0; j < 16; j++)
#pragma unroll
            for (int e = 0; e < 4; e++) acc[mi][j][e] = 0.f;

    for (int s = 0; s < 4; s++) {
        if (s) __syncthreads();
        for (int i = t; i < 2304; i += 256) {
            const void* src = (i < 1152)
                ? (const void*)((const uint4*)(packA + s * 4608) + i)
                : (const void*)((const uint4*)(packB + s * 4608) + (i - 1152));
            cp16(Wsa + i * 16, src);
        }
        cpcommit();
        if (t < 128) {
            const float4* row = (const float4*)(in + (size_t)t * 128 + s * 32);
#pragma unroll
            for (int g = 0; g < 8; g++) {
                float4 a = row[g];
                uint4 o = { f2tf(a.x), f2tf(a.y), f2tf(a.z), f2tf(a.w) };
                *(uint4*)&A_f[bgrp + (g * 4 + sub) * 32 + gid4] = o;
            }
        }
        cpwait<0>();
        __syncthreads();
        mma_slab(acc, A_f + rowgrp * 1024, W_s + pk * 4608, lane, 0);
    }
    float* outX = pk ? outB : outA;
#pragma unroll
    for (int mi = 0; mi < 2; mi++) {
        int r0 = rowgrp * 32 + mi * 16 + gid;
#pragma unroll
        for (int j = 0; j < 16; j++) {
            int c = j * 8 + 2 * t4;
            float b0 = bias_s[pk * 128 + c], b1 = bias_s[pk * 128 + c + 1];
            *(float2*)&outX[(size_t)r0 * 128 + c] =
                make_float2(acc[mi][j][0] + b0, acc[mi][j][1] + b1);
            *(float2*)&outX[(size_t)(r0 + 8) * 128 + c] =
                make_float2(acc[mi][j][2] + b0, acc[mi][j][3] + b1);
        }
    }
}

// ---------------------------------------------------------------------------
// main: one CTA per (bt, 4-n block) = 128 pairs x 128 cols. 128 thr, 4 warps.
// A fragments for GEMM1 built DIRECTLY in registers (n fixed per warp):
//   frag(row m, k) = p_w[k]*v_m[k]  or  |p_w[k]-v_m[k]|
// smem floats: Wbuf 2x4608u @0 | b1 @9216 | b2 @9344 | alias @9472:
//   phase1: v 32x132, V1 32x132, p 4x132, P1 4x132   phase2: h_f 16384u
// total 103424 B -> 2 CTAs/SM
// ---------------------------------------------------------------------------
__global__ __launch_bounds__(128) void pair_main_kernel(
    const float* __restrict__ b1v, const float* __restrict__ b2v,
    float* __restrict__ out) {
    extern __shared__ float sm[];
    unsigned* Wbuf = (unsigned*)sm;
    float* b1_s = sm + 9216;
    float* b2_s = sm + 9344;
    float* AL   = sm + 9472;
    float*    v_s  = AL;            // 32 x 132
    float*    V1_s = AL + 4224;     // 32 x 132
    float*    p_s  = AL + 8448;     // 4 x 132
    float*    P1_s = AL + 8976;     // 4 x 132
    unsigned* h_f  = (unsigned*)AL; // phase 2 alias (16384 u32)

    const int bt = blockIdx.x >> 3, pb = blockIdx.x & 7;
    const int t = threadIdx.x, w = t >> 5, lane = t & 31;
    const int gid = lane >> 2, t4 = lane & 3;
    uint32_t Wba = (uint32_t)__cvta_generic_to_shared(Wbuf);

    // prefetch W1 slab 0 -> buf 0
    for (int i = t; i < 1152; i += 128) cp16(Wba + i * 16, (const uint4*)g_W1f + i);
    cpcommit();

    {   // tile loads
        const float4* vg  = (const float4*)(g_v  + (size_t)bt * 4096);
        const float4* V1g = (const float4*)(g_V1 + (size_t)bt * 4096);
        for (int i = t; i < 1024; i += 128) {
            int m = i >> 5, k4 = (i & 31) * 4;
            *(float4*)&v_s [m * 132 + k4] = vg[i];
            *(float4*)&V1_s[m * 132 + k4] = V1g[i];
        }
        const float4* pg  = (const float4*)(g_p  + (size_t)(bt * 32 + pb * 4) * 128);
        const float4* P1g = (const float4*)(g_P1 + (size_t)(bt * 32 + pb * 4) * 128);
        {
            int n = t >> 5, k4 = (t & 31) * 4;
            *(float4*)&p_s [n * 132 + k4] = pg[t];
            *(float4*)&P1_s[n * 132 + k4] = P1g[t];
        }
        b1_s[t] = b1v[t];
        b2_s[t] = b2v[t];
    }

    float acc[2][16][4];
#pragma unroll
    for (int mi = 0; mi < 2; mi++)
#pragma unroll
        for (int j = 0; j < 16; j++)
#pragma unroll
            for (int e = 0; e < 4; e++) acc[mi][j][e] = 0.f;

    // ---------------- GEMM1: K=256 (prod slabs 0-3, absdiff 4-7) -----------
    // single-barrier cp.async ring: prefetch issued AFTER the barrier.
#pragma unroll 1
    for (int s = 0; s < 8; s++) {
        cpwait<0>();
        __syncthreads();
        {   // prefetch next slab (W2 slab 0 when s==7)
            const uint4* nxt = (s < 7) ? (const uint4*)(g_W1f + (s + 1) * 4608)
                                       : (const uint4*)g_W2f;
            uint32_t dst = Wba + (((s + 1) & 1) * 18432);
            for (int i = t; i < 1152; i += 128) cp16(dst + i * 16, nxt + i);
            cpcommit();
        }
        // build A fragments in registers
        unsigned af[4][2][4];
        {
            const int kb0 = (s & 3) * 32;
            const float* pw = p_s + w * 132 + kb0 + t4;
            const float* vv = v_s + gid * 132 + kb0 + t4;
#pragma unroll
            for (int ks = 0; ks < 4; ks++) {
                float pa = pw[ks * 8], pb = pw[ks * 8 + 4];
#pragma unroll
                for (int mi = 0; mi < 2; mi++) {
                    const float* vb = vv + mi * 2112;   // +16 rows
                    float v00 = vb[ks * 8];
                    float v10 = vb[1056 + ks * 8];      // +8 rows
                    float v01 = vb[ks * 8 + 4];
                    float v11 = vb[1056 + ks * 8 + 4];
                    if (s < 4) {
                        af[ks][mi][0] = f2tf(pa * v00);
                        af[ks][mi][1] = f2tf(pa * v10);
                        af[ks][mi][2] = f2tf(pb * v01);
                        af[ks][mi][3] = f2tf(pb * v11);
                    } else {
                        af[ks][mi][0] = f2tf(fabsf(pa - v00));
                        af[ks][mi][1] = f2tf(fabsf(pa - v10));
                        af[ks][mi][2] = f2tf(fabsf(pb - v01));
                        af[ks][mi][3] = f2tf(fabsf(pb - v11));
                    }
                }
            }
        }
        mma_slab_r(acc, af, Wbuf + (s & 1) * 4608, lane);
    }

    // ------------- epilogue 1: + P1[w] + V1[m] + b1, SiLU ------------------
#pragma unroll
    for (int mi = 0; mi < 2; mi++) {
        int m0 = mi * 16 + gid, m1 = m0 + 8;
#pragma unroll
        for (int j = 0; j < 16; j++) {
            int c0 = j * 8 + 2 * t4;
#pragma unroll
            for (int e = 0; e < 4; e++) {
                int mm = (e < 2) ? m0 : m1;
                int cc = c0 + (e & 1);
                float x = acc[mi][j][e] + P1_s[w * 132 + cc] + V1_s[mm * 132 + cc] + b1_s[cc];
                acc[mi][j][e] = x / (1.f + __expf(-x));
            }
        }
    }
    __syncthreads();   // done reading phase-1 alias buffers

    // stage h in GEMM2 fragment order, pre-converted to tf32
#pragma unroll
    for (int mi = 0; mi < 2; mi++) {
#pragma unroll
        for (int j = 0; j < 16; j++) {
            int kq = j * 2 + (t4 >> 1);
            int base = w * 4096 + kq * 128 + gid * 4 + 2 * (t4 & 1);
            uint2 lo = { f2tf(acc[mi][j][0]), f2tf(acc[mi][j][1]) };
            uint2 hi = { f2tf(acc[mi][j][2]), f2tf(acc[mi][j][3]) };
            *(uint2*)&h_f[base + (mi * 2 + 0) * 32] = lo;
            *(uint2*)&h_f[base + (mi * 2 + 1) * 32] = hi;
        }
    }
#pragma unroll
    for (int mi = 0; mi < 2; mi++)
#pragma unroll
        for (int j = 0; j < 16; j++)
#pragma unroll
            for (int e = 0; e < 4; e++) acc[mi][j][e] = 0.f;

    // ---------------- GEMM2: h(128x128) @ W2 -------------------------------
#pragma unroll 1
    for (int s2 = 0; s2 < 4; s2++) {
        cpwait<0>();
        __syncthreads();   // also publishes h_f on s2==0
        if (s2 < 3) {
            uint32_t dst = Wba + (((s2 + 1) & 1) * 18432);
            const uint4* nxt = (const uint4*)(g_W2f + (s2 + 1) * 4608);
            for (int i = t; i < 1152; i += 128) cp16(dst + i * 16, nxt + i);
            cpcommit();
        }
        mma_slab(acc, h_f + w * 4096, Wbuf + (s2 & 1) * 4608, lane, s2 * 8);
    }

    // ------------- epilogue 2: + b2, direct sector-aligned stores ----------
    const size_t ob = (size_t)blockIdx.x * 16384;
#pragma unroll
    for (int mi = 0; mi < 2; mi++) {
        float* o0 = out + ob + (size_t)(w * 32 + mi * 16 + gid) * 128;
        float* o1 = o0 + 8 * 128;
#pragma unroll
        for (int j = 0; j < 16; j++) {
            int c = j * 8 + 2 * t4;
            *(float2*)&o0[c] = make_float2(acc[mi][j][0] + b2_s[c],
                                           acc[mi][j][1] + b2_s[c + 1]);
            *(float2*)&o1[c] = make_float2(acc[mi][j][2] + b2_s[c],
                                           acc[mi][j][3] + b2_s[c + 1]);
        }
    }
}

// ---------------------------------------------------------------------------
extern "C" void kernel_launch(void* const* d_in, const int* in_sizes, int n_in,
                              void* d_out, int out_size) {
    const float* price  = (const float*)d_in[0];
    const float* liquid = (const float*)d_in[1];
    const float* W_p    = (const float*)d_in[2];
    const float* b_p    = (const float*)d_in[3];
    const float* W_v    = (const float*)d_in[4];
    const float* b_v    = (const float*)d_in[5];
    const float* W1     = (const float*)d_in[6];
    const float* b1     = (const float*)d_in[7];
    const float* W2     = (const float*)d_in[8];
    const float* b2     = (const float*)d_in[9];
    float* out = (float*)d_out;

    cudaFuncSetAttribute(pv_kernel,
                         cudaFuncAttributeMaxDynamicSharedMemorySize, 55296);
    cudaFuncSetAttribute(pair_main_kernel,
                         cudaFuncAttributeMaxDynamicSharedMemorySize, 104448);

    prep_kernel<<<16, 256>>>(W_p, b_p, W_v, b_v, W1);
    pack_kernel<<<28, 128>>>(W1, W2, W_p, W_v);
    pv_kernel<<<128, 256, 54272>>>(price, liquid, b_p, b_v);
    pair_main_kernel<<<2048, 128, 103424>>>(b1, b2, out);
}

// round 7
// speedup vs baseline: 3.2559x; 1.2226x over previous
#include <cuda_runtime.h>
#include <cstdint>
#define DI __device__ __forceinline__

__device__ float g_p [8192*128];
__device__ float g_v [8192*128];
__device__ float g_P1[8192*128];
__device__ float g_V1[8192*128];
__device__ float g_Wfp[128*128];
__device__ float g_Wfv[128*128];
__device__ float g_biasF[2*128];
// tf32 fragment packs for pv prologue (k32 slabs, stride 36)
__device__ __align__(16) unsigned g_Wpf [4*4608];
__device__ __align__(16) unsigned g_Wfpf[4*4608];
__device__ __align__(16) unsigned g_Wvf [4*4608];
__device__ __align__(16) unsigned g_Wfvf[4*4608];
// fp16 fragment packs for main kernel (k64 slabs, stride 36):
//   dst[(ks*32+lane)*36 + 2j + r] = half2(W[16ks+2t4+8r][8j+gid], W[..+1][..])
__device__ __align__(16) unsigned g_W1h[4*4608];   // W1c|W1d rows 256..511
__device__ __align__(16) unsigned g_W2h[2*4608];

DI unsigned f2tf(float x){ unsigned r; asm("cvt.rna.tf32.f32 %0, %1;":"=r"(r):"f"(x)); return r; }
DI unsigned pk2(float lo, float hi){
    unsigned r;
    asm("cvt.rn.f16x2.f32 %0, %1, %2;" : "=r"(r) : "f"(hi), "f"(lo));
    return r;
}
DI void mma8(float* c, unsigned a0,unsigned a1,unsigned a2,unsigned a3,unsigned b0,unsigned b1){
    asm volatile("mma.sync.aligned.m16n8k8.row.col.f32.tf32.tf32.f32 "
        "{%0,%1,%2,%3},{%4,%5,%6,%7},{%8,%9},{%0,%1,%2,%3};\n"
        :"+f"(c[0]),"+f"(c[1]),"+f"(c[2]),"+f"(c[3])
        :"r"(a0),"r"(a1),"r"(a2),"r"(a3),"r"(b0),"r"(b1)); }
DI void mma16(float* c, unsigned a0,unsigned a1,unsigned a2,unsigned a3,unsigned b0,unsigned b1){
    asm volatile("mma.sync.aligned.m16n8k16.row.col.f32.f16.f16.f32 "
        "{%0,%1,%2,%3},{%4,%5,%6,%7},{%8,%9},{%0,%1,%2,%3};\n"
        :"+f"(c[0]),"+f"(c[1]),"+f"(c[2]),"+f"(c[3])
        :"r"(a0),"r"(a1),"r"(a2),"r"(a3),"r"(b0),"r"(b1)); }
DI void cp16(uint32_t s,const void* g){ asm volatile("cp.async.cg.shared.global [%0], [%1], 16;\n"::"r"(s),"l"(g)); }
DI void cpcommit(){ asm volatile("cp.async.commit_group;\n"); }
template<int N> DI void cpwait(){ asm volatile("cp.async.wait_group %0;\n"::"n"(N)); }
DI uint32_t s2u(const void* p){ uint32_t a; asm("{ .reg .u64 t; cvta.to.shared.u64 t, %1; cvt.u32.u64 %0, t; }":"=r"(a):"l"(p)); return a; }

// tf32 slab mma for pv kernel (unchanged, proven)
DI void mma_slab(float (*acc)[16][4], const unsigned* Ab, const unsigned* Wb, int lane){
#pragma unroll
    for(int ks=0; ks<4; ks++){
        unsigned a[2][4];
#pragma unroll
        for(int mi=0; mi<2; mi++){
            int c0 = ks*8 + mi*2;
            a[mi][0]=Ab[(c0+0)*32+lane]; a[mi][1]=Ab[(c0+1)*32+lane];
            a[mi][2]=Ab[(c0+4)*32+lane]; a[mi][3]=Ab[(c0+5)*32+lane];
        }
        const uint4* bb = (const uint4*)(Wb + (ks*32+lane)*36);
#pragma unroll
        for(int jj=0; jj<8; jj++){
            uint4 b = bb[jj];
            mma8(acc[0][2*jj],  a[0][0],a[0][1],a[0][2],a[0][3],b.x,b.y);
            mma8(acc[1][2*jj],  a[1][0],a[1][1],a[1][2],a[1][3],b.x,b.y);
            mma8(acc[0][2*jj+1],a[0][0],a[0][1],a[0][2],a[0][3],b.z,b.w);
            mma8(acc[1][2*jj+1],a[1][0],a[1][1],a[1][2],a[1][3],b.z,b.w);
        }
    }
}

__global__ __launch_bounds__(256) void prep_kernel(
    const float* __restrict__ Wp, const float* __restrict__ bp,
    const float* __restrict__ Wv, const float* __restrict__ bv,
    const float* __restrict__ W1){
    __shared__ float Wc_s[32*128];
    __shared__ float Wr_s[16*128];
    int cb = blockIdx.x, isv = cb>=8, rb = (cb&7)*16;
    const float* Wx  = isv? Wv: Wp;
    const float* W1x = W1 + (isv? 128*128: 0);
    float* outW = isv? g_Wfv: g_Wfp;
    int t = threadIdx.x;
    for(int i=t; i<16*128; i+=256) Wr_s[i] = Wx[(rb+(i>>7))*128 + (i&127)];
    float acc[8];
#pragma unroll
    for(int ii=0; ii<8; ii++) acc[ii]=0.f;
    int j = t&127, ih = (t>>7)*8;
    for(int kc=0; kc<4; kc++){
        __syncthreads();
        for(int i=t; i<32*128; i+=256) Wc_s[i] = W1x[(kc*32+(i>>7))*128 + (i&127)];
        __syncthreads();
        for(int k=0; k<32; k++){
            float b = Wc_s[k*128+j];
#pragma unroll
            for(int ii=0; ii<8; ii++) acc[ii] += Wr_s[(ih+ii)*128 + kc*32+k]*b;
        }
    }
#pragma unroll
    for(int ii=0; ii<8; ii++) outW[(rb+ih+ii)*128 + j] = acc[ii];
    if((cb&7)==0 && t<128){
        const float* bx = isv? bv: bp;
        float s=0.f;
        for(int k=0;k<128;k++) s += bx[k]*W1x[k*128+t];
        g_biasF[isv*128+t] = s;
    }
}

__global__ __launch_bounds__(128) void pack_kernel(
    const float* __restrict__ Wp, const float* __restrict__ Wv){
    int sid = blockIdx.x;
    const float* src; unsigned* dst;
    if      (sid<4) { src = Wp + sid*32*128;          dst = g_Wpf  + sid*4608; }
    else if (sid<8) { src = g_Wfp + (sid-4)*32*128;   dst = g_Wfpf + (sid-4)*4608; }
    else if (sid<12){ src = Wv + (sid-8)*32*128;      dst = g_Wvf  + (sid-8)*4608; }
    else            { src = g_Wfv + (sid-12)*32*128;  dst = g_Wfvf + (sid-12)*4608; }
    int t=threadIdx.x, lane=t&31, ks=t>>5, gid=lane>>2, t4=lane&3;
#pragma unroll
    for(int j=0;j<16;j++)
#pragma unroll
        for(int r=0;r<2;r++)
            dst[(ks*32+lane)*36 + 2*j + r] = f2tf(src[(ks*8+t4+r*4)*128 + j*8 + gid]);
}

// fp16 fragment pack for main-kernel weights. grid 6 x 128.
__global__ __launch_bounds__(128) void pack16_kernel(
    const float* __restrict__ W1, const float* __restrict__ W2){
    int sid = blockIdx.x;
    const float* src; unsigned* dst;
    if(sid<4){ src = W1 + (256 + sid*64)*128; dst = g_W1h + sid*4608; }
    else     { src = W2 + (sid-4)*64*128;     dst = g_W2h + (sid-4)*4608; }
    int t=threadIdx.x, lane=t&31, ks=t>>5, gid=lane>>2, t4=lane&3;
#pragma unroll
    for(int j=0;j<16;j++)
#pragma unroll
        for(int r=0;r<2;r++){
            int k0 = ks*16 + 2*t4 + 8*r;
            dst[(ks*32+lane)*36 + 2*j + r] =
                pk2(src[k0*128 + 8*j + gid], src[(k0+1)*128 + 8*j + gid]);
        }
}

__global__ __launch_bounds__(256) void pv_kernel(
    const float* __restrict__ price, const float* __restrict__ liquid,
    const float* __restrict__ bp, const float* __restrict__ bv){
    extern __shared__ float smpv[];
    unsigned* W_s = (unsigned*)smpv;
    unsigned* A_f = (unsigned*)smpv + 9216;
    float* bias_s = smpv + 13312;
    int cb=blockIdx.x, isv=cb>=64, rb=(cb&63)*128;
    const float* in = (isv? liquid: price) + (size_t)rb*128;
    const unsigned* pA = isv? g_Wvf : g_Wpf;
    const unsigned* pB = isv? g_Wfvf: g_Wfpf;
    float* outA = (isv? g_v : g_p)  + (size_t)rb*128;
    float* outB = (isv? g_V1: g_P1) + (size_t)rb*128;
    int t=threadIdx.x, w=t>>5, lane=t&31, gid=lane>>2, t4=lane&3;
    if(t<128) bias_s[t] = isv? bv[t]: bp[t];
    else      bias_s[t] = g_biasF[isv*128 + (t-128)];
    uint32_t Wsa = s2u(W_s);
    int sub=((t&31)>>4)*2 + ((t&15)>>3), gid4=(t&7)*4, bgrp=(t>>5)*1024;
    int rowgrp=w&3, pk=w>>2;
    float acc[2][16][4];
#pragma unroll
    for(int mi=0;mi<2;mi++)
#pragma unroll
        for(int j=0;j<16;j++)
#pragma unroll
            for(int e=0;e<4;e++) acc[mi][j][e]=0.f;
    for(int s=0;s<4;s++){
        if(s) __syncthreads();
        for(int i=t;i<2304;i+=256){
            const void* src = (i<1152)? (const void*)((const uint4*)(pA+s*4608)+i)
                                      : (const void*)((const uint4*)(pB+s*4608)+(i-1152));
            cp16(Wsa + i*16, src);
        }
        cpcommit();
        if(t<128){
            const float4* row = (const float4*)(in + (size_t)t*128 + s*32);
#pragma unroll
            for(int g=0;g<8;g++){
                float4 a=row[g];
                uint4 o={f2tf(a.x),f2tf(a.y),f2tf(a.z),f2tf(a.w)};
                *(uint4*)&A_f[bgrp + (g*4+sub)*32 + gid4] = o;
            }
        }
        cpwait<0>();
        __syncthreads();
        mma_slab(acc, A_f + rowgrp*1024, W_s + pk*4608, lane);
    }
    float* outX = pk? outB: outA;
#pragma unroll
    for(int mi=0;mi<2;mi++){
        int r0 = rowgrp*32 + mi*16 + gid;
#pragma unroll
        for(int j=0;j<16;j++){
            int c=j*8+2*t4;
            float b0=bias_s[pk*128+c], b1=bias_s[pk*128+c+1];
            *(float2*)&outX[(size_t)r0*128+c]     = make_float2(acc[mi][j][0]+b0, acc[mi][j][1]+b1);
            *(float2*)&outX[(size_t)(r0+8)*128+c] = make_float2(acc[mi][j][2]+b0, acc[mi][j][3]+b1);
        }
    }
}

// ---------------------------------------------------------------------------
// main (fp16 m16n8k16): CTA = (bt, 4-n block) = 128 pairs x 128 cols; 4 warps.
// GEMM1: 4 k64 slabs (prod k0-127, absdiff k0-127), A fragments in registers.
// GEMM2: A = silu output packed to half2 in registers (layout matches!).
// smem floats: Wbuf 9216 | b1 9216+ | b2 | v 9472(32x132) | V1 13696 |
//   p 17920(4x132) | P1 18448 .. 18976  = 75904 B -> 2 CTAs/SM
// ---------------------------------------------------------------------------
__global__ __launch_bounds__(128) void pair_main_kernel(
    const float* __restrict__ b1v, const float* __restrict__ b2v,
    float* __restrict__ out){
    extern __shared__ float sm[];
    unsigned* Wbuf = (unsigned*)sm;
    float* b1_s = sm + 9216;
    float* b2_s = sm + 9344;
    float* v_s  = sm + 9472;
    float* V1_s = sm + 13696;
    float* p_s  = sm + 17920;
    float* P1_s = sm + 18448;
    const int bt=blockIdx.x>>3, pb=blockIdx.x&7;
    const int t=threadIdx.x, w=t>>5, lane=t&31;
    const int gid=lane>>2, t4=lane&3;
    uint32_t Wba = s2u(Wbuf);

    for(int i=t;i<1152;i+=128) cp16(Wba+i*16, (const uint4*)g_W1h+i);
    cpcommit();
    {
        const float4* vg  = (const float4*)(g_v  + (size_t)bt*4096);
        const float4* V1g = (const float4*)(g_V1 + (size_t)bt*4096);
        for(int i=t;i<1024;i+=128){
            int m=i>>5, k4=(i&31)*4;
            *(float4*)&v_s [m*132+k4] = vg[i];
            *(float4*)&V1_s[m*132+k4] = V1g[i];
        }
        const float4* pg  = (const float4*)(g_p  + (size_t)(bt*32+pb*4)*128);
        const float4* P1g = (const float4*)(g_P1 + (size_t)(bt*32+pb*4)*128);
        int n=t>>5, k4=(t&31)*4;
        *(float4*)&p_s [n*132+k4] = pg[t];
        *(float4*)&P1_s[n*132+k4] = P1g[t];
        b1_s[t]=b1v[t]; b2_s[t]=b2v[t];
    }

    float acc[2][16][4];
#pragma unroll
    for(int mi=0;mi<2;mi++)
#pragma unroll
        for(int j=0;j<16;j++)
#pragma unroll
            for(int e=0;e<4;e++) acc[mi][j][e]=0.f;

    // ---------------- GEMM1: 4 slabs of k64 ----------------
#pragma unroll 1
    for(int s=0;s<4;s++){
        cpwait<0>();
        __syncthreads();
        {   // prefetch next slab (W2 slab0 when s==3)
            const uint4* nxt = (s<3)? (const uint4*)(g_W1h+(s+1)*4608)
                                    : (const uint4*)g_W2h;
            uint32_t dst = Wba + (((s+1)&1)*18432);
            for(int i=t;i<1152;i+=128) cp16(dst+i*16, nxt+i);
            cpcommit();
        }
        unsigned ah[4][2][4];
        {
            const int kb0=(s&1)*64;
            const float* pw = p_s + w*132 + kb0;
#pragma unroll
            for(int ks=0;ks<4;ks++){
                int ko = ks*16 + 2*t4;
                float2 pl = *(const float2*)&pw[ko];
                float2 ph = *(const float2*)&pw[ko+8];
#pragma unroll
                for(int mi=0;mi<2;mi++){
                    const float* v0 = v_s + (mi*16+gid)*132 + kb0;
                    const float* v1 = v0 + 8*132;
                    float2 a0=*(const float2*)&v0[ko],   b0=*(const float2*)&v1[ko];
                    float2 a1=*(const float2*)&v0[ko+8], b1=*(const float2*)&v1[ko+8];
                    if(s<2){
                        ah[ks][mi][0]=pk2(pl.x*a0.x, pl.y*a0.y);
                        ah[ks][mi][1]=pk2(pl.x*b0.x, pl.y*b0.y);
                        ah[ks][mi][2]=pk2(ph.x*a1.x, ph.y*a1.y);
                        ah[ks][mi][3]=pk2(ph.x*b1.x, ph.y*b1.y);
                    }else{
                        ah[ks][mi][0]=pk2(fabsf(pl.x-a0.x), fabsf(pl.y-a0.y));
                        ah[ks][mi][1]=pk2(fabsf(pl.x-b0.x), fabsf(pl.y-b0.y));
                        ah[ks][mi][2]=pk2(fabsf(ph.x-a1.x), fabsf(ph.y-a1.y));
                        ah[ks][mi][3]=pk2(fabsf(ph.x-b1.x), fabsf(ph.y-b1.y));
                    }
                }
            }
        }
        const unsigned* Wb = Wbuf + (s&1)*4608;
#pragma unroll
        for(int ks=0;ks<4;ks++){
            const uint4* bb = (const uint4*)(Wb + (ks*32+lane)*36);
#pragma unroll
            for(int jj=0;jj<8;jj++){
                uint4 b = bb[jj];
                mma16(acc[0][2*jj],  ah[ks][0][0],ah[ks][0][1],ah[ks][0][2],ah[ks][0][3],b.x,b.y);
                mma16(acc[1][2*jj],  ah[ks][1][0],ah[ks][1][1],ah[ks][1][2],ah[ks][1][3],b.x,b.y);
                mma16(acc[0][2*jj+1],ah[ks][0][0],ah[ks][0][1],ah[ks][0][2],ah[ks][0][3],b.z,b.w);
                mma16(acc[1][2*jj+1],ah[ks][1][0],ah[ks][1][1],ah[ks][1][2],ah[ks][1][3],b.z,b.w);
            }
        }
    }

    // ------- epilogue 1: silu(D + P1 + V1 + b1) -> half2 regs (GEMM2 A) ----
    unsigned h2[2][16][2];
#pragma unroll
    for(int mi=0;mi<2;mi++){
#pragma unroll
        for(int j=0;j<16;j++){
            int c0=j*8+2*t4;
            float2 P =*(const float2*)&P1_s[w*132+c0];
            float2 Bb=*(const float2*)&b1_s[c0];
            float2 V0=*(const float2*)&V1_s[(mi*16+gid)*132+c0];
            float2 V1r=*(const float2*)&V1_s[(mi*16+gid+8)*132+c0];
            float x0=acc[mi][j][0]+P.x+V0.x+Bb.x;
            float x1=acc[mi][j][1]+P.y+V0.y+Bb.y;
            float x2=acc[mi][j][2]+P.x+V1r.x+Bb.x;
            float x3=acc[mi][j][3]+P.y+V1r.y+Bb.y;
            x0=x0/(1.f+__expf(-x0)); x1=x1/(1.f+__expf(-x1));
            x2=x2/(1.f+__expf(-x2)); x3=x3/(1.f+__expf(-x3));
            h2[mi][j][0]=pk2(x0,x1);
            h2[mi][j][1]=pk2(x2,x3);
            acc[mi][j][0]=0.f; acc[mi][j][1]=0.f;
            acc[mi][j][2]=0.f; acc[mi][j][3]=0.f;
        }
    }

    // ---------------- GEMM2: 2 slabs of k64, A from h2 regs ----------------
#pragma unroll 1
    for(int s2=0;s2<2;s2++){
        cpwait<0>();
        __syncthreads();
        if(s2==0){
            uint32_t dst = Wba + 18432;
            const uint4* nxt = (const uint4*)(g_W2h + 4608);
            for(int i=t;i<1152;i+=128) cp16(dst+i*16, nxt+i);
            cpcommit();
        }
        const unsigned* Wb = Wbuf + (s2&1)*4608;
#pragma unroll
        for(int ks=0;ks<4;ks++){
            int kg = s2*4+ks;
            const uint4* bb = (const uint4*)(Wb + (ks*32+lane)*36);
#pragma unroll
            for(int jj=0;jj<8;jj++){
                uint4 b = bb[jj];
                mma16(acc[0][2*jj],  h2[0][2*kg][0],h2[0][2*kg][1],h2[0][2*kg+1][0],h2[0][2*kg+1][1],b.x,b.y);
                mma16(acc[1][2*jj],  h2[1][2*kg][0],h2[1][2*kg][1],h2[1][2*kg+1][0],h2[1][2*kg+1][1],b.x,b.y);
                mma16(acc[0][2*jj+1],h2[0][2*kg][0],h2[0][2*kg][1],h2[0][2*kg+1][0],h2[0][2*kg+1][1],b.z,b.w);
                mma16(acc[1][2*jj+1],h2[1][2*kg][0],h2[1][2*kg][1],h2[1][2*kg+1][0],h2[1][2*kg+1][1],b.z,b.w);
            }
        }
    }

    // ------------- epilogue 2: + b2, direct stores ----------------
    const size_t ob = (size_t)blockIdx.x*16384;
#pragma unroll
    for(int mi=0;mi<2;mi++){
        float* o0 = out + ob + (size_t)(w*32+mi*16+gid)*128;
        float* o1 = o0 + 1024;
#pragma unroll
        for(int j=0;j<16;j++){
            int c=j*8+2*t4;
            *(float2*)&o0[c] = make_float2(acc[mi][j][0]+b2_s[c], acc[mi][j][1]+b2_s[c+1]);
            *(float2*)&o1[c] = make_float2(acc[mi][j][2]+b2_s[c], acc[mi][j][3]+b2_s[c+1]);
        }
    }
}

extern "C" void kernel_launch(void* const* d_in, const int* in_sizes, int n_in,
                              void* d_out, int out_size){
    const float* price =(const float*)d_in[0];
    const float* liquid=(const float*)d_in[1];
    const float* W_p=(const float*)d_in[2];
    const float* b_p=(const float*)d_in[3];
    const float* W_v=(const float*)d_in[4];
    const float* b_v=(const float*)d_in[5];
    const float* W1 =(const float*)d_in[6];
    const float* b1 =(const float*)d_in[7];
    const float* W2 =(const float*)d_in[8];
    const float* b2 =(const float*)d_in[9];
    float* out=(float*)d_out;
    cudaFuncSetAttribute(pv_kernel, cudaFuncAttributeMaxDynamicSharedMemorySize, 55296);
    cudaFuncSetAttribute(pair_main_kernel, cudaFuncAttributeMaxDynamicSharedMemorySize, 76800);
    prep_kernel<<<16, 256>>>(W_p, b_p, W_v, b_v, W1);
    pack_kernel<<<16, 128>>>(W_p, W_v);
    pack16_kernel<<<6, 128>>>(W1, W2);
    pv_kernel<<<128, 256, 54272>>>(price, liquid, b_p, b_v);
    pair_main_kernel<<<2048, 128, 75904>>>(b1, b2, out);
}

// round 8
// speedup vs baseline: 3.8212x; 1.1736x over previous
#include <cuda_runtime.h>
#include <cstdint>
#define DI __device__ __forceinline__

__device__ float g_p [8192*128];
__device__ float g_v [8192*128];
__device__ float g_P1[8192*128];
__device__ float g_V1[8192*128];
__device__ float g_Wfp[128*128];
__device__ float g_Wfv[128*128];
__device__ float g_biasF[2*128];
// tf32 fragment packs for pv prologue (k32 slabs, stride 36)
__device__ __align__(16) unsigned g_Wpf [4*4608];
__device__ __align__(16) unsigned g_Wfpf[4*4608];
__device__ __align__(16) unsigned g_Wvf [4*4608];
__device__ __align__(16) unsigned g_Wfvf[4*4608];
// fp16 fragment packs for main kernel (k64 slabs, stride 36)
__device__ __align__(16) unsigned g_W1h[4*4608];   // W1c|W1d rows 256..511
__device__ __align__(16) unsigned g_W2h[2*4608];

DI unsigned f2tf(float x){ unsigned r; asm("cvt.rna.tf32.f32 %0, %1;":"=r"(r):"f"(x)); return r; }
DI unsigned pk2(float lo, float hi){
    unsigned r;
    asm("cvt.rn.f16x2.f32 %0, %1, %2;" : "=r"(r) : "f"(hi), "f"(lo));
    return r;
}
DI void mma8(float* c, unsigned a0,unsigned a1,unsigned a2,unsigned a3,unsigned b0,unsigned b1){
    asm volatile("mma.sync.aligned.m16n8k8.row.col.f32.tf32.tf32.f32 "
        "{%0,%1,%2,%3},{%4,%5,%6,%7},{%8,%9},{%0,%1,%2,%3};\n"
        :"+f"(c[0]),"+f"(c[1]),"+f"(c[2]),"+f"(c[3])
        :"r"(a0),"r"(a1),"r"(a2),"r"(a3),"r"(b0),"r"(b1)); }
DI void mma16(float* c, unsigned a0,unsigned a1,unsigned a2,unsigned a3,unsigned b0,unsigned b1){
    asm volatile("mma.sync.aligned.m16n8k16.row.col.f32.f16.f16.f32 "
        "{%0,%1,%2,%3},{%4,%5,%6,%7},{%8,%9},{%0,%1,%2,%3};\n"
        :"+f"(c[0]),"+f"(c[1]),"+f"(c[2]),"+f"(c[3])
        :"r"(a0),"r"(a1),"r"(a2),"r"(a3),"r"(b0),"r"(b1)); }
DI void cp16(uint32_t s,const void* g){ asm volatile("cp.async.cg.shared.global [%0], [%1], 16;\n"::"r"(s),"l"(g)); }
DI void cpcommit(){ asm volatile("cp.async.commit_group;\n"); }
template<int N> DI void cpwait(){ asm volatile("cp.async.wait_group %0;\n"::"n"(N)); }
DI uint32_t s2u(const void* p){ uint32_t a; asm("{ .reg .u64 t; cvta.to.shared.u64 t, %1; cvt.u32.u64 %0, t; }":"=r"(a):"l"(p)); return a; }

// tf32 slab mma for pv kernel (unchanged, proven)
DI void mma_slab(float (*acc)[16][4], const unsigned* Ab, const unsigned* Wb, int lane){
#pragma unroll
    for(int ks=0; ks<4; ks++){
        unsigned a[2][4];
#pragma unroll
        for(int mi=0; mi<2; mi++){
            int c0 = ks*8 + mi*2;
            a[mi][0]=Ab[(c0+0)*32+lane]; a[mi][1]=Ab[(c0+1)*32+lane];
            a[mi][2]=Ab[(c0+4)*32+lane]; a[mi][3]=Ab[(c0+5)*32+lane];
        }
        const uint4* bb = (const uint4*)(Wb + (ks*32+lane)*36);
#pragma unroll
        for(int jj=0; jj<8; jj++){
            uint4 b = bb[jj];
            mma8(acc[0][2*jj],  a[0][0],a[0][1],a[0][2],a[0][3],b.x,b.y);
            mma8(acc[1][2*jj],  a[1][0],a[1][1],a[1][2],a[1][3],b.x,b.y);
            mma8(acc[0][2*jj+1],a[0][0],a[0][1],a[0][2],a[0][3],b.z,b.w);
            mma8(acc[1][2*jj+1],a[1][0],a[1][1],a[1][2],a[1][3],b.z,b.w);
        }
    }
}

__global__ __launch_bounds__(256) void prep_kernel(
    const float* __restrict__ Wp, const float* __restrict__ bp,
    const float* __restrict__ Wv, const float* __restrict__ bv,
    const float* __restrict__ W1){
    __shared__ float Wc_s[32*128];
    __shared__ float Wr_s[16*128];
    int cb = blockIdx.x, isv = cb>=8, rb = (cb&7)*16;
    const float* Wx  = isv? Wv: Wp;
    const float* W1x = W1 + (isv? 128*128: 0);
    float* outW = isv? g_Wfv: g_Wfp;
    int t = threadIdx.x;
    for(int i=t; i<16*128; i+=256) Wr_s[i] = Wx[(rb+(i>>7))*128 + (i&127)];
    float acc[8];
#pragma unroll
    for(int ii=0; ii<8; ii++) acc[ii]=0.f;
    int j = t&127, ih = (t>>7)*8;
    for(int kc=0; kc<4; kc++){
        __syncthreads();
        for(int i=t; i<32*128; i+=256) Wc_s[i] = W1x[(kc*32+(i>>7))*128 + (i&127)];
        __syncthreads();
        for(int k=0; k<32; k++){
            float b = Wc_s[k*128+j];
#pragma unroll
            for(int ii=0; ii<8; ii++) acc[ii] += Wr_s[(ih+ii)*128 + kc*32+k]*b;
        }
    }
#pragma unroll
    for(int ii=0; ii<8; ii++) outW[(rb+ih+ii)*128 + j] = acc[ii];
    if((cb&7)==0 && t<128){
        const float* bx = isv? bv: bp;
        float s=0.f;
        for(int k=0;k<128;k++) s += bx[k]*W1x[k*128+t];
        g_biasF[isv*128+t] = s;
    }
}

__global__ __launch_bounds__(128) void pack_kernel(
    const float* __restrict__ Wp, const float* __restrict__ Wv){
    int sid = blockIdx.x;
    const float* src; unsigned* dst;
    if      (sid<4) { src = Wp + sid*32*128;          dst = g_Wpf  + sid*4608; }
    else if (sid<8) { src = g_Wfp + (sid-4)*32*128;   dst = g_Wfpf + (sid-4)*4608; }
    else if (sid<12){ src = Wv + (sid-8)*32*128;      dst = g_Wvf  + (sid-8)*4608; }
    else            { src = g_Wfv + (sid-12)*32*128;  dst = g_Wfvf + (sid-12)*4608; }
    int t=threadIdx.x, lane=t&31, ks=t>>5, gid=lane>>2, t4=lane&3;
#pragma unroll
    for(int j=0;j<16;j++)
#pragma unroll
        for(int r=0;r<2;r++)
            dst[(ks*32+lane)*36 + 2*j + r] = f2tf(src[(ks*8+t4+r*4)*128 + j*8 + gid]);
}

// fp16 fragment pack for main-kernel weights. grid 6 x 128.
__global__ __launch_bounds__(128) void pack16_kernel(
    const float* __restrict__ W1, const float* __restrict__ W2){
    int sid = blockIdx.x;
    const float* src; unsigned* dst;
    if(sid<4){ src = W1 + (256 + sid*64)*128; dst = g_W1h + sid*4608; }
    else     { src = W2 + (sid-4)*64*128;     dst = g_W2h + (sid-4)*4608; }
    int t=threadIdx.x, lane=t&31, ks=t>>5, gid=lane>>2, t4=lane&3;
#pragma unroll
    for(int j=0;j<16;j++)
#pragma unroll
        for(int r=0;r<2;r++){
            int k0 = ks*16 + 2*t4 + 8*r;
            dst[(ks*32+lane)*36 + 2*j + r] =
                pk2(src[k0*128 + 8*j + gid], src[(k0+1)*128 + 8*j + gid]);
        }
}

__global__ __launch_bounds__(256) void pv_kernel(
    const float* __restrict__ price, const float* __restrict__ liquid,
    const float* __restrict__ bp, const float* __restrict__ bv){
    extern __shared__ float smpv[];
    unsigned* W_s = (unsigned*)smpv;
    unsigned* A_f = (unsigned*)smpv + 9216;
    float* bias_s = smpv + 13312;
    int cb=blockIdx.x, isv=cb>=64, rb=(cb&63)*128;
    const float* in = (isv? liquid: price) + (size_t)rb*128;
    const unsigned* pA = isv? g_Wvf : g_Wpf;
    const unsigned* pB = isv? g_Wfvf: g_Wfpf;
    float* outA = (isv? g_v : g_p)  + (size_t)rb*128;
    float* outB = (isv? g_V1: g_P1) + (size_t)rb*128;
    int t=threadIdx.x, w=t>>5, lane=t&31, gid=lane>>2, t4=lane&3;
    if(t<128) bias_s[t] = isv? bv[t]: bp[t];
    else      bias_s[t] = g_biasF[isv*128 + (t-128)];
    uint32_t Wsa = s2u(W_s);
    int sub=((t&31)>>4)*2 + ((t&15)>>3), gid4=(t&7)*4, bgrp=(t>>5)*1024;
    int rowgrp=w&3, pk=w>>2;
    float acc[2][16][4];
#pragma unroll
    for(int mi=0;mi<2;mi++)
#pragma unroll
        for(int j=0;j<16;j++)
#pragma unroll
            for(int e=0;e<4;e++) acc[mi][j][e]=0.f;
    for(int s=0;s<4;s++){
        if(s) __syncthreads();
        for(int i=t;i<2304;i+=256){
            const void* src = (i<1152)? (const void*)((const uint4*)(pA+s*4608)+i)
                                      : (const void*)((const uint4*)(pB+s*4608)+(i-1152));
            cp16(Wsa + i*16, src);
        }
        cpcommit();
        if(t<128){
            const float4* row = (const float4*)(in + (size_t)t*128 + s*32);
#pragma unroll
            for(int g=0;g<8;g++){
                float4 a=row[g];
                uint4 o={f2tf(a.x),f2tf(a.y),f2tf(a.z),f2tf(a.w)};
                *(uint4*)&A_f[bgrp + (g*4+sub)*32 + gid4] = o;
            }
        }
        cpwait<0>();
        __syncthreads();
        mma_slab(acc, A_f + rowgrp*1024, W_s + pk*4608, lane);
    }
    float* outX = pk? outB: outA;
#pragma unroll
    for(int mi=0;mi<2;mi++){
        int r0 = rowgrp*32 + mi*16 + gid;
#pragma unroll
        for(int j=0;j<16;j++){
            int c=j*8+2*t4;
            float b0=bias_s[pk*128+c], b1=bias_s[pk*128+c+1];
            *(float2*)&outX[(size_t)r0*128+c]     = make_float2(acc[mi][j][0]+b0, acc[mi][j][1]+b1);
            *(float2*)&outX[(size_t)(r0+8)*128+c] = make_float2(acc[mi][j][2]+b0, acc[mi][j][3]+b1);
        }
    }
}

// ---------------------------------------------------------------------------
// main (fp16 m16n8k16), 256 thr / 8 warps: warp w owns 16 pair-rows
//   [w*16, w*16+16): n = w>>1, m = (w&1)*16 + 0..15. acc = 64 regs.
// smem floats: Wbuf 9216u | b1 9216 | b2 9344 | v 9472 (32x136) | V1 13824 |
//   p 18176 (4x136) | P1 18720 .. 19264 = 77056 B -> 2 CTAs/SM (16 warps)
// ---------------------------------------------------------------------------
__global__ __launch_bounds__(256,2) void pair_main_kernel(
    const float* __restrict__ b1v, const float* __restrict__ b2v,
    float* __restrict__ out){
    extern __shared__ float sm[];
    unsigned* Wbuf = (unsigned*)sm;
    float* b1_s = sm + 9216;
    float* b2_s = sm + 9344;
    float* v_s  = sm + 9472;
    float* V1_s = sm + 13824;
    float* p_s  = sm + 18176;
    float* P1_s = sm + 18720;
    const int bt=blockIdx.x>>3, pb=blockIdx.x&7;
    const int t=threadIdx.x, w=t>>5, lane=t&31;
    const int gid=lane>>2, t4=lane&3;
    const int n = w>>1, mbase = (w&1)*16;
    uint32_t Wba = s2u(Wbuf);

    for(int i=t;i<1152;i+=256) cp16(Wba+i*16, (const uint4*)g_W1h+i);
    cpcommit();
    {
        const float4* vg  = (const float4*)(g_v  + (size_t)bt*4096);
        const float4* V1g = (const float4*)(g_V1 + (size_t)bt*4096);
        for(int i=t;i<1024;i+=256){
            int m=i>>5, k4=(i&31)*4;
            *(float4*)&v_s [m*136+k4] = vg[i];
            *(float4*)&V1_s[m*136+k4] = V1g[i];
        }
        const float4* pg  = (const float4*)(g_p  + (size_t)(bt*32+pb*4)*128);
        const float4* P1g = (const float4*)(g_P1 + (size_t)(bt*32+pb*4)*128);
        if(t<128){
            int nn=t>>5, k4=(t&31)*4;
            *(float4*)&p_s [nn*136+k4] = pg[t];
            *(float4*)&P1_s[nn*136+k4] = P1g[t];
            b1_s[t]=b1v[t]; b2_s[t]=b2v[t];
        }
    }

    float acc[16][4];
#pragma unroll
    for(int j=0;j<16;j++)
#pragma unroll
        for(int e=0;e<4;e++) acc[j][e]=0.f;

    // ---------------- GEMM1: 4 slabs of k64 ----------------
#pragma unroll 1
    for(int s=0;s<4;s++){
        cpwait<0>();
        __syncthreads();
        {   // prefetch next slab (W2 slab0 when s==3)
            const uint4* nxt = (s<3)? (const uint4*)(g_W1h+(s+1)*4608)
                                    : (const uint4*)g_W2h;
            uint32_t dst = Wba + (((s+1)&1)*18432);
            for(int i=t;i<1152;i+=256) cp16(dst+i*16, nxt+i);
            cpcommit();
        }
        unsigned ah[4][4];
        {
            const int kb0=(s&1)*64;
            const float* pw = p_s + n*136 + kb0;
            const float* v0 = v_s + (mbase+gid)*136 + kb0;
            const float* v1 = v0 + 8*136;
#pragma unroll
            for(int ks=0;ks<4;ks++){
                int ko = ks*16 + 2*t4;
                float2 pl = *(const float2*)&pw[ko];
                float2 ph = *(const float2*)&pw[ko+8];
                float2 a0=*(const float2*)&v0[ko],   b0=*(const float2*)&v1[ko];
                float2 a1=*(const float2*)&v0[ko+8], b1=*(const float2*)&v1[ko+8];
                if(s<2){
                    ah[ks][0]=pk2(pl.x*a0.x, pl.y*a0.y);
                    ah[ks][1]=pk2(pl.x*b0.x, pl.y*b0.y);
                    ah[ks][2]=pk2(ph.x*a1.x, ph.y*a1.y);
                    ah[ks][3]=pk2(ph.x*b1.x, ph.y*b1.y);
                }else{
                    ah[ks][0]=pk2(fabsf(pl.x-a0.x), fabsf(pl.y-a0.y));
                    ah[ks][1]=pk2(fabsf(pl.x-b0.x), fabsf(pl.y-b0.y));
                    ah[ks][2]=pk2(fabsf(ph.x-a1.x), fabsf(ph.y-a1.y));
                    ah[ks][3]=pk2(fabsf(ph.x-b1.x), fabsf(ph.y-b1.y));
                }
            }
        }
        const unsigned* Wb = Wbuf + (s&1)*4608;
#pragma unroll
        for(int ks=0;ks<4;ks++){
            const uint4* bb = (const uint4*)(Wb + (ks*32+lane)*36);
#pragma unroll
            for(int jj=0;jj<8;jj++){
                uint4 b = bb[jj];
                mma16(acc[2*jj],  ah[ks][0],ah[ks][1],ah[ks][2],ah[ks][3],b.x,b.y);
                mma16(acc[2*jj+1],ah[ks][0],ah[ks][1],ah[ks][2],ah[ks][3],b.z,b.w);
            }
        }
    }

    // ------- epilogue 1: silu(D + P1 + V1 + b1) -> half2 regs (GEMM2 A) ----
    unsigned h2[16][2];
#pragma unroll
    for(int j=0;j<16;j++){
        int c0=j*8+2*t4;
        float2 P  =*(const float2*)&P1_s[n*136+c0];
        float2 Bb =*(const float2*)&b1_s[c0];
        float2 V0 =*(const float2*)&V1_s[(mbase+gid)*136+c0];
        float2 V1r=*(const float2*)&V1_s[(mbase+gid+8)*136+c0];
        float x0=acc[j][0]+P.x+V0.x+Bb.x;
        float x1=acc[j][1]+P.y+V0.y+Bb.y;
        float x2=acc[j][2]+P.x+V1r.x+Bb.x;
        float x3=acc[j][3]+P.y+V1r.y+Bb.y;
        x0=x0/(1.f+__expf(-x0)); x1=x1/(1.f+__expf(-x1));
        x2=x2/(1.f+__expf(-x2)); x3=x3/(1.f+__expf(-x3));
        h2[j][0]=pk2(x0,x1);
        h2[j][1]=pk2(x2,x3);
        acc[j][0]=0.f; acc[j][1]=0.f; acc[j][2]=0.f; acc[j][3]=0.f;
    }

    // ---------------- GEMM2: 2 slabs of k64, A from h2 regs ----------------
#pragma unroll 1
    for(int s2=0;s2<2;s2++){
        cpwait<0>();
        __syncthreads();
        if(s2==0){
            uint32_t dst = Wba + 18432;
            const uint4* nxt = (const uint4*)(g_W2h + 4608);
            for(int i=t;i<1152;i+=256) cp16(dst+i*16, nxt+i);
            cpcommit();
        }
        const unsigned* Wb = Wbuf + (s2&1)*4608;
#pragma unroll
        for(int ks=0;ks<4;ks++){
            int kg = s2*4+ks;
            const uint4* bb = (const uint4*)(Wb + (ks*32+lane)*36);
#pragma unroll
            for(int jj=0;jj<8;jj++){
                uint4 b = bb[jj];
                mma16(acc[2*jj],  h2[2*kg][0],h2[2*kg][1],h2[2*kg+1][0],h2[2*kg+1][1],b.x,b.y);
                mma16(acc[2*jj+1],h2[2*kg][0],h2[2*kg][1],h2[2*kg+1][0],h2[2*kg+1][1],b.z,b.w);
            }
        }
    }

    // ------------- epilogue 2: + b2, direct stores ----------------
    const size_t ob = (size_t)blockIdx.x*16384;
    float* o0 = out + ob + (size_t)(w*16+gid)*128;
    float* o1 = o0 + 1024;
#pragma unroll
    for(int j=0;j<16;j++){
        int c=j*8+2*t4;
        *(float2*)&o0[c] = make_float2(acc[j][0]+b2_s[c], acc[j][1]+b2_s[c+1]);
        *(float2*)&o1[c] = make_float2(acc[j][2]+b2_s[c], acc[j][3]+b2_s[c+1]);
    }
}

extern "C" void kernel_launch(void* const* d_in, const int* in_sizes, int n_in,
                              void* d_out, int out_size){
    const float* price =(const float*)d_in[0];
    const float* liquid=(const float*)d_in[1];
    const float* W_p=(const float*)d_in[2];
    const float* b_p=(const float*)d_in[3];
    const float* W_v=(const float*)d_in[4];
    const float* b_v=(const float*)d_in[5];
    const float* W1 =(const float*)d_in[6];
    const float* b1 =(const float*)d_in[7];
    const float* W2 =(const float*)d_in[8];
    const float* b2 =(const float*)d_in[9];
    float* out=(float*)d_out;
    cudaFuncSetAttribute(pv_kernel, cudaFuncAttributeMaxDynamicSharedMemorySize, 55296);
    cudaFuncSetAttribute(pair_main_kernel, cudaFuncAttributeMaxDynamicSharedMemorySize, 77824);
    prep_kernel<<<16, 256>>>(W_p, b_p, W_v, b_v, W1);
    pack_kernel<<<16, 128>>>(W_p, W_v);
    pack16_kernel<<<6, 128>>>(W1, W2);
    pv_kernel<<<128, 256, 54272>>>(price, liquid, b_p, b_v);
    pair_main_kernel<<<2048, 256, 77056>>>(b1, b2, out);
}

// round 10
// speedup vs baseline: 3.8602x; 1.0102x over previous
#include <cuda_runtime.h>
#include <cstdint>
#define DI __device__ __forceinline__

__device__ float g_p [8192*128];
__device__ float g_v [8192*128];
__device__ float g_P1[8192*128];
__device__ float g_V1[8192*128];
__device__ float g_Wfp[128*128];
__device__ float g_Wfv[128*128];
__device__ float g_biasF[2*128];
// tf32 fragment packs for pv prologue (k32 slabs, stride 36)
__device__ __align__(16) unsigned g_Wpf [4*4608];
__device__ __align__(16) unsigned g_Wfpf[4*4608];
__device__ __align__(16) unsigned g_Wvf [4*4608];
__device__ __align__(16) unsigned g_Wfvf[4*4608];
// fp16 fragment packs for main kernel (k64 slabs, stride 36)
__device__ __align__(16) unsigned g_W1h[4*4608];   // W1c|W1d rows 256..511
__device__ __align__(16) unsigned g_W2h[2*4608];

DI unsigned f2tf(float x){ unsigned r; asm("cvt.rna.tf32.f32 %0, %1;":"=r"(r):"f"(x)); return r; }
DI unsigned pk2(float lo, float hi){
    unsigned r;
    asm("cvt.rn.f16x2.f32 %0, %1, %2;" : "=r"(r) : "f"(hi), "f"(lo));
    return r;
}
DI void mma8(float* c, unsigned a0,unsigned a1,unsigned a2,unsigned a3,unsigned b0,unsigned b1){
    asm volatile("mma.sync.aligned.m16n8k8.row.col.f32.tf32.tf32.f32 "
        "{%0,%1,%2,%3},{%4,%5,%6,%7},{%8,%9},{%0,%1,%2,%3};\n"
        :"+f"(c[0]),"+f"(c[1]),"+f"(c[2]),"+f"(c[3])
        :"r"(a0),"r"(a1),"r"(a2),"r"(a3),"r"(b0),"r"(b1)); }
DI void mma16(float* c, unsigned a0,unsigned a1,unsigned a2,unsigned a3,unsigned b0,unsigned b1){
    asm volatile("mma.sync.aligned.m16n8k16.row.col.f32.f16.f16.f32 "
        "{%0,%1,%2,%3},{%4,%5,%6,%7},{%8,%9},{%0,%1,%2,%3};\n"
        :"+f"(c[0]),"+f"(c[1]),"+f"(c[2]),"+f"(c[3])
        :"r"(a0),"r"(a1),"r"(a2),"r"(a3),"r"(b0),"r"(b1)); }
DI void cp16(uint32_t s,const void* g){ asm volatile("cp.async.cg.shared.global [%0], [%1], 16;\n"::"r"(s),"l"(g)); }
DI void cpcommit(){ asm volatile("cp.async.commit_group;\n"); }
template<int N> DI void cpwait(){ asm volatile("cp.async.wait_group %0;\n"::"n"(N)); }
DI uint32_t s2u(const void* p){ uint32_t a; asm("{ .reg .u64 t; cvta.to.shared.u64 t, %1; cvt.u32.u64 %0, t; }":"=r"(a):"l"(p)); return a; }

// tf32 slab mma for pv kernel (unchanged, proven)
DI void mma_slab(float (*acc)[16][4], const unsigned* Ab, const unsigned* Wb, int lane){
#pragma unroll
    for(int ks=0; ks<4; ks++){
        unsigned a[2][4];
#pragma unroll
        for(int mi=0; mi<2; mi++){
            int c0 = ks*8 + mi*2;
            a[mi][0]=Ab[(c0+0)*32+lane]; a[mi][1]=Ab[(c0+1)*32+lane];
            a[mi][2]=Ab[(c0+4)*32+lane]; a[mi][3]=Ab[(c0+5)*32+lane];
        }
        const uint4* bb = (const uint4*)(Wb + (ks*32+lane)*36);
#pragma unroll
        for(int jj=0; jj<8; jj++){
            uint4 b = bb[jj];
            mma8(acc[0][2*jj],  a[0][0],a[0][1],a[0][2],a[0][3],b.x,b.y);
            mma8(acc[1][2*jj],  a[1][0],a[1][1],a[1][2],a[1][3],b.x,b.y);
            mma8(acc[0][2*jj+1],a[0][0],a[0][1],a[0][2],a[0][3],b.z,b.w);
            mma8(acc[1][2*jj+1],a[1][0],a[1][1],a[1][2],a[1][3],b.z,b.w);
        }
    }
}

__global__ __launch_bounds__(256) void prep_kernel(
    const float* __restrict__ Wp, const float* __restrict__ bp,
    const float* __restrict__ Wv, const float* __restrict__ bv,
    const float* __restrict__ W1){
    __shared__ float Wc_s[32*128];
    __shared__ float Wr_s[16*128];
    int cb = blockIdx.x, isv = cb>=8, rb = (cb&7)*16;
    const float* Wx  = isv? Wv: Wp;
    const float* W1x = W1 + (isv? 128*128: 0);
    float* outW = isv? g_Wfv: g_Wfp;
    int t = threadIdx.x;
    for(int i=t; i<16*128; i+=256) Wr_s[i] = Wx[(rb+(i>>7))*128 + (i&127)];
    float acc[8];
#pragma unroll
    for(int ii=0; ii<8; ii++) acc[ii]=0.f;
    int j = t&127, ih = (t>>7)*8;
    for(int kc=0; kc<4; kc++){
        __syncthreads();
        for(int i=t; i<32*128; i+=256) Wc_s[i] = W1x[(kc*32+(i>>7))*128 + (i&127)];
        __syncthreads();
        for(int k=0; k<32; k++){
            float b = Wc_s[k*128+j];
#pragma unroll
            for(int ii=0; ii<8; ii++) acc[ii] += Wr_s[(ih+ii)*128 + kc*32+k]*b;
        }
    }
#pragma unroll
    for(int ii=0; ii<8; ii++) outW[(rb+ih+ii)*128 + j] = acc[ii];
    if((cb&7)==0 && t<128){
        const float* bx = isv? bv: bp;
        float s=0.f;
        for(int k=0;k<128;k++) s += bx[k]*W1x[k*128+t];
        g_biasF[isv*128+t] = s;
    }
}

__global__ __launch_bounds__(128) void pack_kernel(
    const float* __restrict__ Wp, const float* __restrict__ Wv){
    int sid = blockIdx.x;
    const float* src; unsigned* dst;
    if      (sid<4) { src = Wp + sid*32*128;          dst = g_Wpf  + sid*4608; }
    else if (sid<8) { src = g_Wfp + (sid-4)*32*128;   dst = g_Wfpf + (sid-4)*4608; }
    else if (sid<12){ src = Wv + (sid-8)*32*128;      dst = g_Wvf  + (sid-8)*4608; }
    else            { src = g_Wfv + (sid-12)*32*128;  dst = g_Wfvf + (sid-12)*4608; }
    int t=threadIdx.x, lane=t&31, ks=t>>5, gid=lane>>2, t4=lane&3;
#pragma unroll
    for(int j=0;j<16;j++)
#pragma unroll
        for(int r=0;r<2;r++)
            dst[(ks*32+lane)*36 + 2*j + r] = f2tf(src[(ks*8+t4+r*4)*128 + j*8 + gid]);
}

// fp16 fragment pack for main-kernel weights. grid 6 x 128.
__global__ __launch_bounds__(128) void pack16_kernel(
    const float* __restrict__ W1, const float* __restrict__ W2){
    int sid = blockIdx.x;
    const float* src; unsigned* dst;
    if(sid<4){ src = W1 + (256 + sid*64)*128; dst = g_W1h + sid*4608; }
    else     { src = W2 + (sid-4)*64*128;     dst = g_W2h + (sid-4)*4608; }
    int t=threadIdx.x, lane=t&31, ks=t>>5, gid=lane>>2, t4=lane&3;
#pragma unroll
    for(int j=0;j<16;j++)
#pragma unroll
        for(int r=0;r<2;r++){
            int k0 = ks*16 + 2*t4 + 8*r;
            dst[(ks*32+lane)*36 + 2*j + r] =
                pk2(src[k0*128 + 8*j + gid], src[(k0+1)*128 + 8*j + gid]);
        }
}

__global__ __launch_bounds__(256) void pv_kernel(
    const float* __restrict__ price, const float* __restrict__ liquid,
    const float* __restrict__ bp, const float* __restrict__ bv){
    extern __shared__ float smpv[];
    unsigned* W_s = (unsigned*)smpv;
    unsigned* A_f = (unsigned*)smpv + 9216;
    float* bias_s = smpv + 13312;
    int cb=blockIdx.x, isv=cb>=64, rb=(cb&63)*128;
    const float* in = (isv? liquid: price) + (size_t)rb*128;
    const unsigned* pA = isv? g_Wvf : g_Wpf;
    const unsigned* pB = isv? g_Wfvf: g_Wfpf;
    float* outA = (isv? g_v : g_p)  + (size_t)rb*128;
    float* outB = (isv? g_V1: g_P1) + (size_t)rb*128;
    int t=threadIdx.x, w=t>>5, lane=t&31, gid=lane>>2, t4=lane&3;
    if(t<128) bias_s[t] = isv? bv[t]: bp[t];
    else      bias_s[t] = g_biasF[isv*128 + (t-128)];
    uint32_t Wsa = s2u(W_s);
    int sub=((t&31)>>4)*2 + ((t&15)>>3), gid4=(t&7)*4, bgrp=(t>>5)*1024;
    int rowgrp=w&3, pk=w>>2;
    float acc[2][16][4];
#pragma unroll
    for(int mi=0;mi<2;mi++)
#pragma unroll
        for(int j=0;j<16;j++)
#pragma unroll
            for(int e=0;e<4;e++) acc[mi][j][e]=0.f;
    for(int s=0;s<4;s++){
        if(s) __syncthreads();
        for(int i=t;i<2304;i+=256){
            const void* src = (i<1152)? (const void*)((const uint4*)(pA+s*4608)+i)
                                      : (const void*)((const uint4*)(pB+s*4608)+(i-1152));
            cp16(Wsa + i*16, src);
        }
        cpcommit();
        if(t<128){
            const float4* row = (const float4*)(in + (size_t)t*128 + s*32);
#pragma unroll
            for(int g=0;g<8;g++){
                float4 a=row[g];
                uint4 o={f2tf(a.x),f2tf(a.y),f2tf(a.z),f2tf(a.w)};
                *(uint4*)&A_f[bgrp + (g*4+sub)*32 + gid4] = o;
            }
        }
        cpwait<0>();
        __syncthreads();
        mma_slab(acc, A_f + rowgrp*1024, W_s + pk*4608, lane);
    }
    float* outX = pk? outB: outA;
#pragma unroll
    for(int mi=0;mi<2;mi++){
        int r0 = rowgrp*32 + mi*16 + gid;
#pragma unroll
        for(int j=0;j<16;j++){
            int c=j*8+2*t4;
            float b0=bias_s[pk*128+c], b1=bias_s[pk*128+c+1];
            *(float2*)&outX[(size_t)r0*128+c]     = make_float2(acc[mi][j][0]+b0, acc[mi][j][1]+b1);
            *(float2*)&outX[(size_t)(r0+8)*128+c] = make_float2(acc[mi][j][2]+b0, acc[mi][j][3]+b1);
        }
    }
}

// A-fragment build for one k64 slab (s: 0/1 prod k0-63/k64-127, 2/3 absdiff).
// Base pointers pw/v0/v1 MUST already include the per-thread +2*t4 offset.
DI void buildA(unsigned ah[4][4], const float* pw, const float* v0, const float* v1, int s){
    const int kb0 = (s&1)*64;
    const float* pwk = pw + kb0;
    const float* v0k = v0 + kb0;
    const float* v1k = v1 + kb0;
#pragma unroll
    for(int ks=0;ks<4;ks++){
        int ko = ks*16;
        float2 pl = *(const float2*)&pwk[ko];
        float2 ph = *(const float2*)&pwk[ko+8];
        float2 a0=*(const float2*)&v0k[ko],   b0=*(const float2*)&v1k[ko];
        float2 a1=*(const float2*)&v0k[ko+8], b1=*(const float2*)&v1k[ko+8];
        if(s<2){
            ah[ks][0]=pk2(pl.x*a0.x, pl.y*a0.y);
            ah[ks][1]=pk2(pl.x*b0.x, pl.y*b0.y);
            ah[ks][2]=pk2(ph.x*a1.x, ph.y*a1.y);
            ah[ks][3]=pk2(ph.x*b1.x, ph.y*b1.y);
        }else{
            ah[ks][0]=pk2(fabsf(pl.x-a0.x), fabsf(pl.y-a0.y));
            ah[ks][1]=pk2(fabsf(pl.x-b0.x), fabsf(pl.y-b0.y));
            ah[ks][2]=pk2(fabsf(ph.x-a1.x), fabsf(ph.y-a1.y));
            ah[ks][3]=pk2(fabsf(ph.x-b1.x), fabsf(ph.y-b1.y));
        }
    }
}

DI void mmaW(float (*acc)[4], const unsigned ah[4][4], const unsigned* Wb, int lane){
#pragma unroll
    for(int ks=0;ks<4;ks++){
        const uint4* bb = (const uint4*)(Wb + (ks*32+lane)*36);
#pragma unroll
        for(int jj=0;jj<8;jj++){
            uint4 b = bb[jj];
            mma16(acc[2*jj],  ah[ks][0],ah[ks][1],ah[ks][2],ah[ks][3],b.x,b.y);
            mma16(acc[2*jj+1],ah[ks][0],ah[ks][1],ah[ks][2],ah[ks][3],b.z,b.w);
        }
    }
}

DI void mmaH(float (*acc)[4], const unsigned h2[16][2], int s2, const unsigned* Wb, int lane){
#pragma unroll
    for(int ks=0;ks<4;ks++){
        int kg = s2*4+ks;
        const uint4* bb = (const uint4*)(Wb + (ks*32+lane)*36);
#pragma unroll
        for(int jj=0;jj<8;jj++){
            uint4 b = bb[jj];
            mma16(acc[2*jj],  h2[2*kg][0],h2[2*kg][1],h2[2*kg+1][0],h2[2*kg+1][1],b.x,b.y);
            mma16(acc[2*jj+1],h2[2*kg][0],h2[2*kg][1],h2[2*kg+1][0],h2[2*kg+1][1],b.z,b.w);
        }
    }
}

// ---------------------------------------------------------------------------
// main (fp16 m16n8k16), 256 thr / 8 warps, 4-slab W ring, 4 sync points.
// smem floats: Wbuf 18432u @0 | b1 @18432 | b2 @18560 | v @18688 (32x136) |
//   V1 @23040 | p @27392 (4x136) | P1 @27936 .. 28480 = 113920 B -> 2 CTAs/SM
// ---------------------------------------------------------------------------
__global__ __launch_bounds__(256,2) void pair_main_kernel(
    const float* __restrict__ b1v, const float* __restrict__ b2v,
    float* __restrict__ out){
    extern __shared__ float sm[];
    unsigned* Wbuf = (unsigned*)sm;
    float* b1_s = sm + 18432;
    float* b2_s = sm + 18560;
    float* v_s  = sm + 18688;
    float* V1_s = sm + 23040;
    float* p_s  = sm + 27392;
    float* P1_s = sm + 27936;
    const int bt=blockIdx.x>>3, pb=blockIdx.x&7;
    const int t=threadIdx.x, w=t>>5, lane=t&31;
    const int gid=lane>>2, t4=lane&3;
    const int n = w>>1, mbase = (w&1)*16;
    uint32_t Wba = s2u(Wbuf);

    // group A: W1 slabs 0,1 -> slots 0,1 ; group B: W1 slabs 2,3 -> slots 2,3
    for(int i=t;i<2304;i+=256) cp16(Wba+i*16, (const uint4*)g_W1h+i);
    cpcommit();
    for(int i=t;i<2304;i+=256) cp16(Wba+36864+i*16, (const uint4*)g_W1h+2304+i);
    cpcommit();
    {
        const float4* vg  = (const float4*)(g_v  + (size_t)bt*4096);
        const float4* V1g = (const float4*)(g_V1 + (size_t)bt*4096);
        for(int i=t;i<1024;i+=256){
            int m=i>>5, k4=(i&31)*4;
            *(float4*)&v_s [m*136+k4] = vg[i];
            *(float4*)&V1_s[m*136+k4] = V1g[i];
        }
        const float4* pg  = (const float4*)(g_p  + (size_t)(bt*32+pb*4)*128);
        const float4* P1g = (const float4*)(g_P1 + (size_t)(bt*32+pb*4)*128);
        if(t<128){
            int nn=t>>5, k4=(t&31)*4;
            *(float4*)&p_s [nn*136+k4] = pg[t];
            *(float4*)&P1_s[nn*136+k4] = P1g[t];
            b1_s[t]=b1v[t]; b2_s[t]=b2v[t];
        }
    }
    __syncthreads();   // publish tiles (p_s/v_s) for A-builds

    // per-thread fragment bases INCLUDE the lane k-offset 2*t4 (round-9 bug fix)
    const float* pw = p_s + n*136 + 2*t4;
    const float* v0 = v_s + (mbase+gid)*136 + 2*t4;
    const float* v1 = v0 + 8*136;

    float acc[16][4];
#pragma unroll
    for(int j=0;j<16;j++)
#pragma unroll
        for(int e=0;e<4;e++) acc[j][e]=0.f;

    unsigned ah[4][4];

    // ---- pair 0: W1 slabs 0,1 (slots 0,1) ----
    buildA(ah, pw, v0, v1, 0);      // overlaps group-A flight
    cpwait<1>();
    __syncthreads();
    mmaW(acc, ah, Wbuf, lane);
    buildA(ah, pw, v0, v1, 1);
    mmaW(acc, ah, Wbuf+4608, lane);

    // ---- pair 1: W1 slabs 2,3 (slots 2,3); refill slots 0,1 with W2 ----
    buildA(ah, pw, v0, v1, 2);
    cpwait<0>();
    __syncthreads();                 // all warps done with slots 0,1
    for(int i=t;i<2304;i+=256) cp16(Wba+i*16, (const uint4*)g_W2h+i);
    cpcommit();
    mmaW(acc, ah, Wbuf+2*4608, lane);
    buildA(ah, pw, v0, v1, 3);
    mmaW(acc, ah, Wbuf+3*4608, lane);

    // ------- epilogue 1: silu(D + P1 + V1 + b1) -> half2 regs (GEMM2 A) ----
    unsigned h2[16][2];
#pragma unroll
    for(int j=0;j<16;j++){
        int c0=j*8+2*t4;
        float2 P  =*(const float2*)&P1_s[n*136+c0];
        float2 Bb =*(const float2*)&b1_s[c0];
        float2 V0 =*(const float2*)&V1_s[(mbase+gid)*136+c0];
        float2 V1r=*(const float2*)&V1_s[(mbase+gid+8)*136+c0];
        float x0=acc[j][0]+P.x+V0.x+Bb.x;
        float x1=acc[j][1]+P.y+V0.y+Bb.y;
        float x2=acc[j][2]+P.x+V1r.x+Bb.x;
        float x3=acc[j][3]+P.y+V1r.y+Bb.y;
        x0=x0/(1.f+__expf(-x0)); x1=x1/(1.f+__expf(-x1));
        x2=x2/(1.f+__expf(-x2)); x3=x3/(1.f+__expf(-x3));
        h2[j][0]=pk2(x0,x1);
        h2[j][1]=pk2(x2,x3);
        acc[j][0]=0.f; acc[j][1]=0.f; acc[j][2]=0.f; acc[j][3]=0.f;
    }

    // ---- pair 2: GEMM2, W2 slabs 0,1 (slots 0,1), A from h2 regs ----
    cpwait<0>();
    __syncthreads();
    mmaH(acc, h2, 0, Wbuf, lane);
    mmaH(acc, h2, 1, Wbuf+4608, lane);

    // ------------- epilogue 2: + b2, direct stores ----------------
    const size_t ob = (size_t)blockIdx.x*16384;
    float* o0 = out + ob + (size_t)(w*16+gid)*128;
    float* o1 = o0 + 1024;
#pragma unroll
    for(int j=0;j<16;j++){
        int c=j*8+2*t4;
        *(float2*)&o0[c] = make_float2(acc[j][0]+b2_s[c], acc[j][1]+b2_s[c+1]);
        *(float2*)&o1[c] = make_float2(acc[j][2]+b2_s[c], acc[j][3]+b2_s[c+1]);
    }
}

extern "C" void kernel_launch(void* const* d_in, const int* in_sizes, int n_in,
                              void* d_out, int out_size){
    const float* price =(const float*)d_in[0];
    const float* liquid=(const float*)d_in[1];
    const float* W_p=(const float*)d_in[2];
    const float* b_p=(const float*)d_in[3];
    const float* W_v=(const float*)d_in[4];
    const float* b_v=(const float*)d_in[5];
    const float* W1 =(const float*)d_in[6];
    const float* b1 =(const float*)d_in[7];
    const float* W2 =(const float*)d_in[8];
    const float* b2 =(const float*)d_in[9];
    float* out=(float*)d_out;
    cudaFuncSetAttribute(pv_kernel, cudaFuncAttributeMaxDynamicSharedMemorySize, 55296);
    cudaFuncSetAttribute(pair_main_kernel, cudaFuncAttributeMaxDynamicSharedMemorySize, 114688);
    prep_kernel<<<16, 256>>>(W_p, b_p, W_v, b_v, W1);
    pack_kernel<<<16, 128>>>(W_p, W_v);
    pack16_kernel<<<6, 128>>>(W1, W2);
    pv_kernel<<<128, 256, 54272>>>(price, liquid, b_p, b_v);
    pair_main_kernel<<<2048, 256, 113920>>>(b1, b2, out);
}